// round 8
// baseline (speedup 1.0000x reference)
#include <cuda_runtime.h>
#include <cuda_bf16.h>
#include <cstdint>

#define BB 4
#define CC 256
#define HWN 16384
#define PP 2048
#define THRV 0.8f

// ---------------- scratch (no allocations allowed) ----------------
__device__ __nv_bfloat16 g_Whi[PP * PP];          // Wadj bf16 hi [o][p]
__device__ __nv_bfloat16 g_Wlo[PP * PP];          // Wadj bf16 lo
__device__ __nv_bfloat16 g_Gthi[BB * CC * PP];    // G^T bf16 hi [b][c][p]
__device__ __nv_bfloat16 g_Gtlo[BB * CC * PP];
__device__ float         g_Gf[BB * PP * CC];      // G fp32 [b][p][c] (residual)
__device__ __nv_bfloat16 g_Zhi[BB * PP * CC];     // stage-1 out bf16 hi [b][p][c]
__device__ __nv_bfloat16 g_Zlo[BB * PP * CC];
__device__ __nv_bfloat16 g_WGhi[CC * CC];         // Wwg bf16 hi [d][c]
__device__ __nv_bfloat16 g_WGlo[CC * CC];
__device__ float         g_R[BB * CC * PP];       // dense stage-2 out [b][d][p]
__device__ int           g_idx[BB * PP];          // topk indices
__device__ int           g_inv[BB * HWN];         // hw -> p rank, or -1

// ---------------- PTX helpers (baseline ISA: sm_80+) ---------------
__device__ __forceinline__ uint32_t smem_u32(const void* p) {
    uint32_t a;
    asm("{ .reg .u64 t; cvta.to.shared.u64 t, %1; cvt.u32.u64 %0, t; }" : "=r"(a) : "l"(p));
    return a;
}
#define CPA16(dst_u32, src_ptr) \
    asm volatile("cp.async.cg.shared.global [%0], [%1], 16;" :: "r"(dst_u32), "l"(src_ptr) : "memory")
#define CPA_COMMIT() asm volatile("cp.async.commit_group;" ::: "memory")
#define CPA_WAIT1()  asm volatile("cp.async.wait_group 1;" ::: "memory")

#define MMA_BF16(c, a0, a1, a2, a3, b0, b1) \
    asm volatile("mma.sync.aligned.m16n8k16.row.col.f32.bf16.bf16.f32 " \
        "{%0,%1,%2,%3}, {%4,%5,%6,%7}, {%8,%9}, {%0,%1,%2,%3};" \
        : "+f"((c)[0]), "+f"((c)[1]), "+f"((c)[2]), "+f"((c)[3]) \
        : "r"(a0), "r"(a1), "r"(a2), "r"(a3), "r"(b0), "r"(b1))

#define LDSM4(r0, r1, r2, r3, addr) \
    asm volatile("ldmatrix.sync.aligned.m8n8.x4.shared.b16 {%0,%1,%2,%3}, [%4];" \
        : "=r"(r0), "=r"(r1), "=r"(r2), "=r"(r3) : "r"(addr))

__device__ __forceinline__ uint32_t pack_hi2(float a, float b) {
    __nv_bfloat162 t = __floats2bfloat162_rn(a, b);
    return *(uint32_t*)&t;
}

// ---------------- fused prep: topk(+inv map) + W splits -------------
// blocks 0..3   : per-batch top-2048 (compact + bitonic) + inv map
// blocks 4..131 : Wadj bf16 hi/lo split (+ Wwg split)
__global__ __launch_bounds__(1024) void prep_kernel(
    const float* __restrict__ edge,
    const float* __restrict__ wadj, const float* __restrict__ wwg)
{
    const int bid = blockIdx.x, tid = threadIdx.x;

    if (bid < 4) {                                // ---- topk ----
        extern __shared__ unsigned long long keys[];   // 8192 max
        __shared__ int cnt;
        const int b = bid;
        const float* e = edge + b * HWN;
        for (int i = tid; i < HWN; i += 1024) g_inv[b * HWN + i] = -1;
        if (tid == 0) cnt = 0;
        __syncthreads();
        for (int i = tid; i < HWN; i += 1024) {
            float v = e[i];
            if (v >= THRV) {
                int pos = atomicAdd(&cnt, 1);
                if (pos < 8192)
                    keys[pos] = ((unsigned long long)__float_as_uint(v) << 32) | (unsigned int)(~i);
            }
        }
        __syncthreads();
        int c = min(cnt, 8192);
        int n = (c <= 4096) ? 4096 : 8192;
        for (int i = c + tid; i < n; i += 1024) keys[i] = 0ull;
        __syncthreads();
        for (int k = 2; k <= n; k <<= 1) {
            for (int j = k >> 1; j > 0; j >>= 1) {
                for (int i = tid; i < n; i += 1024) {
                    int ixj = i ^ j;
                    if (ixj > i) {
                        unsigned long long a = keys[i], cc2 = keys[ixj];
                        bool up = (i & k) == 0;
                        if (up ? (a < cc2) : (a > cc2)) { keys[i] = cc2; keys[ixj] = a; }
                    }
                }
                __syncthreads();
            }
        }
        for (int p = tid; p < PP; p += 1024) {
            int j = (int)(~(unsigned int)(keys[p] & 0xFFFFFFFFu));
            g_idx[b * PP + p] = j;
            g_inv[b * HWN + j] = p;
        }
    } else {                                      // ---- W splits ----
        const int gt = (bid - 4) * 1024 + tid;    // 131072 threads
        const float4* W4 = (const float4*)wadj;   // 1048576 float4
        for (int i = gt; i < PP * PP / 4; i += 128 * 1024) {
            float4 v = W4[i];
            __nv_bfloat16 h0 = __float2bfloat16_rn(v.x), h1 = __float2bfloat16_rn(v.y);
            __nv_bfloat16 h2 = __float2bfloat16_rn(v.z), h3 = __float2bfloat16_rn(v.w);
            uint2 hp, lp;
            hp.x = pack_hi2(v.x, v.y); hp.y = pack_hi2(v.z, v.w);
            lp.x = pack_hi2(v.x - __bfloat162float(h0), v.y - __bfloat162float(h1));
            lp.y = pack_hi2(v.z - __bfloat162float(h2), v.w - __bfloat162float(h3));
            *(uint2*)(g_Whi + (size_t)i * 4) = hp;
            *(uint2*)(g_Wlo + (size_t)i * 4) = lp;
        }
        const float4* G4 = (const float4*)wwg;    // 16384 float4
        if (gt < CC * CC / 4) {
            float4 v = G4[gt];
            __nv_bfloat16 h0 = __float2bfloat16_rn(v.x), h1 = __float2bfloat16_rn(v.y);
            __nv_bfloat16 h2 = __float2bfloat16_rn(v.z), h3 = __float2bfloat16_rn(v.w);
            uint2 hp, lp;
            hp.x = pack_hi2(v.x, v.y); hp.y = pack_hi2(v.z, v.w);
            lp.x = pack_hi2(v.x - __bfloat162float(h0), v.y - __bfloat162float(h1));
            lp.y = pack_hi2(v.z - __bfloat162float(h2), v.w - __bfloat162float(h3));
            *(uint2*)(g_WGhi + (size_t)gt * 4) = hp;
            *(uint2*)(g_WGlo + (size_t)gt * 4) = lp;
        }
    }
}

// ---------------- gather: x -> Gt bf16 hi/lo [c][p] + Gf fp32 [p][c]
__global__ __launch_bounds__(256) void gather_kernel(const float* __restrict__ x)
{
    __shared__ float tile[64][65];
    __shared__ int jj[64];
    const int p0 = blockIdx.x * 64, c0 = blockIdx.y * 64, b = blockIdx.z;
    const int tid = threadIdx.x;
    if (tid < 64) jj[tid] = g_idx[b * PP + p0 + tid];
    __syncthreads();

    #pragma unroll
    for (int e = tid; e < 64 * 64; e += 256) {
        int pc = e & 63, cl = e >> 6;
        tile[pc][cl] = x[((size_t)b * CC + c0 + cl) * HWN + jj[pc]];
    }
    __syncthreads();

    #pragma unroll
    for (int e = tid; e < 64 * 64; e += 256) {
        int cl = e >> 6, pc = e & 63;
        float v = tile[pc][cl];
        __nv_bfloat16 h = __float2bfloat16_rn(v);
        size_t o = ((size_t)b * CC + c0 + cl) * PP + p0 + pc;
        g_Gthi[o] = h;
        g_Gtlo[o] = __float2bfloat16_rn(v - __bfloat162float(h));
    }
    #pragma unroll
    for (int e = tid; e < 64 * 64; e += 256) {
        int pc = e >> 6, cl = e & 63;
        g_Gf[((size_t)b * PP + p0 + pc) * CC + c0 + cl] = tile[pc][cl];
    }
}

// ---------------- mma.sync GEMM geometry ---------------------------
// CTA 128(M) x 64(N), BK=32, 256 thr, warps 2(m) x 4(n), warp 64x16.
// smem stage: Ah/Al [128][40], Bh/Bl [64][40] bf16; 80B padded rows.
#define STAGE 30720
#define ROWE  40

// ---------------- GEMM1: Z = relu(BN(W @ G)) + G --------------------
__global__ __launch_bounds__(256, 2) void gemm1_mma(
    const float* __restrict__ ga, const float* __restrict__ be)
{
    extern __shared__ __align__(16) char sm[];
    const uint32_t sb = smem_u32(sm);
    const int tid = threadIdx.x;
    const int b = blockIdx.z, m0 = blockIdx.y * 128, n0 = blockIdx.x * 64;
    const int lane = tid & 31, warp = tid >> 5;
    const int grp = lane >> 2, qid = lane & 3;
    const int wm = warp >> 2, wn = warp & 3;

    float acc[4][2][4];
    #pragma unroll
    for (int i = 0; i < 4; i++)
        #pragma unroll
        for (int j = 0; j < 2; j++)
            #pragma unroll
            for (int r = 0; r < 4; r++) acc[i][j][r] = 0.0f;

#define G1_FILL(st, k0) do { \
    uint32_t base_ = sb + (st) * STAGE; \
    for (int i_ = tid; i_ < 512; i_ += 256) { \
        int r_ = i_ >> 2, c8_ = (i_ & 3) * 8; \
        uint32_t d_ = base_ + r_ * 80 + c8_ * 2; \
        CPA16(d_,         g_Whi + (size_t)(m0 + r_) * PP + (k0) + c8_); \
        CPA16(d_ + 10240, g_Wlo + (size_t)(m0 + r_) * PP + (k0) + c8_); \
    } \
    { \
        int i_ = tid; \
        int r_ = i_ >> 2, c8_ = (i_ & 3) * 8; \
        uint32_t d_ = base_ + 20480 + r_ * 80 + c8_ * 2; \
        CPA16(d_,        g_Gthi + ((size_t)b * CC + n0 + r_) * PP + (k0) + c8_); \
        CPA16(d_ + 5120, g_Gtlo + ((size_t)b * CC + n0 + r_) * PP + (k0) + c8_); \
    } } while (0)

    G1_FILL(0, 0);
    CPA_COMMIT();

    const int NIT = PP / 32;   // 64
    #pragma unroll 1
    for (int it = 0; it < NIT; it++) {
        if (it + 1 < NIT) G1_FILL((it + 1) & 1, (it + 1) * 32);
        CPA_COMMIT();
        CPA_WAIT1();
        __syncthreads();

        const uint32_t stb = sb + (it & 1) * STAGE;
        #pragma unroll
        for (int kk = 0; kk < 2; kk++) {
            const int kb0 = kk * 16;
            uint32_t ah[4][4], al[4][4], bh[4], bl[4];
            #pragma unroll
            for (int mt = 0; mt < 4; mt++) {
                uint32_t aaddr = stb + ((wm * 64 + mt * 16 + (lane & 15)) * ROWE
                                        + kb0 + ((lane >> 4) << 3)) * 2;
                LDSM4(ah[mt][0], ah[mt][1], ah[mt][2], ah[mt][3], aaddr);
                LDSM4(al[mt][0], al[mt][1], al[mt][2], al[mt][3], aaddr + 10240);
            }
            {
                uint32_t baddr = stb + 20480
                    + ((wn * 16 + ((lane >> 4) << 3) + (lane & 7)) * ROWE
                       + kb0 + (((lane >> 3) & 1) << 3)) * 2;
                LDSM4(bh[0], bh[1], bh[2], bh[3], baddr);
                LDSM4(bl[0], bl[1], bl[2], bl[3], baddr + 5120);
            }
            #pragma unroll
            for (int mt = 0; mt < 4; mt++)
                #pragma unroll
                for (int nt = 0; nt < 2; nt++) {
                    MMA_BF16(acc[mt][nt], ah[mt][0], ah[mt][1], ah[mt][2], ah[mt][3],
                             bh[nt * 2], bh[nt * 2 + 1]);
                    MMA_BF16(acc[mt][nt], al[mt][0], al[mt][1], al[mt][2], al[mt][3],
                             bh[nt * 2], bh[nt * 2 + 1]);
                    MMA_BF16(acc[mt][nt], ah[mt][0], ah[mt][1], ah[mt][2], ah[mt][3],
                             bl[nt * 2], bl[nt * 2 + 1]);
                }
        }
        __syncthreads();
    }

    const float inv = rsqrtf(1.0f + 1e-5f);
    #pragma unroll
    for (int mt = 0; mt < 4; mt++) {
        int row0 = m0 + wm * 64 + mt * 16 + grp;
        int row1 = row0 + 8;
        float s0 = inv * ga[row0], t0 = be[row0];
        float s1 = inv * ga[row1], t1 = be[row1];
        #pragma unroll
        for (int nt = 0; nt < 2; nt++) {
            int col = n0 + wn * 16 + nt * 8 + qid * 2;
            size_t o0 = ((size_t)b * PP + row0) * CC + col;
            size_t o1 = ((size_t)b * PP + row1) * CC + col;
            float2 gf0 = *(const float2*)(g_Gf + o0);
            float2 gf1 = *(const float2*)(g_Gf + o1);
            float v00 = fmaxf(fmaf(acc[mt][nt][0], s0, t0), 0.0f) + gf0.x;
            float v01 = fmaxf(fmaf(acc[mt][nt][1], s0, t0), 0.0f) + gf0.y;
            float v10 = fmaxf(fmaf(acc[mt][nt][2], s1, t1), 0.0f) + gf1.x;
            float v11 = fmaxf(fmaf(acc[mt][nt][3], s1, t1), 0.0f) + gf1.y;
            __nv_bfloat162 h0 = __floats2bfloat162_rn(v00, v01);
            __nv_bfloat162 h1 = __floats2bfloat162_rn(v10, v11);
            *(uint32_t*)(g_Zhi + o0) = *(uint32_t*)&h0;
            *(uint32_t*)(g_Zhi + o1) = *(uint32_t*)&h1;
            __nv_bfloat162 l0 = __floats2bfloat162_rn(v00 - __bfloat162float(h0.x),
                                                      v01 - __bfloat162float(h0.y));
            __nv_bfloat162 l1 = __floats2bfloat162_rn(v10 - __bfloat162float(h1.x),
                                                      v11 - __bfloat162float(h1.y));
            *(uint32_t*)(g_Zlo + o0) = *(uint32_t*)&l0;
            *(uint32_t*)(g_Zlo + o1) = *(uint32_t*)&l1;
        }
    }
#undef G1_FILL
}

// ---------------- GEMM2: R[b][d][p] = relu(BN(WG @ Z^T)), DENSE -----
// M = d (256), N = p (2048), K = c (256)
__global__ __launch_bounds__(256, 2) void gemm2_mma(
    const float* __restrict__ gw, const float* __restrict__ bw)
{
    extern __shared__ __align__(16) char sm[];
    const uint32_t sb = smem_u32(sm);
    const int tid = threadIdx.x;
    const int b = blockIdx.z, m0 = blockIdx.y * 128, n0 = blockIdx.x * 64;
    const int lane = tid & 31, warp = tid >> 5;
    const int grp = lane >> 2, qid = lane & 3;
    const int wm = warp >> 2, wn = warp & 3;

    float acc[4][2][4];
    #pragma unroll
    for (int i = 0; i < 4; i++)
        #pragma unroll
        for (int j = 0; j < 2; j++)
            #pragma unroll
            for (int r = 0; r < 4; r++) acc[i][j][r] = 0.0f;

#define G2_FILL(st, k0) do { \
    uint32_t base_ = sb + (st) * STAGE; \
    for (int i_ = tid; i_ < 512; i_ += 256) { \
        int r_ = i_ >> 2, c8_ = (i_ & 3) * 8; \
        uint32_t d_ = base_ + r_ * 80 + c8_ * 2; \
        CPA16(d_,         g_WGhi + (size_t)(m0 + r_) * CC + (k0) + c8_); \
        CPA16(d_ + 10240, g_WGlo + (size_t)(m0 + r_) * CC + (k0) + c8_); \
    } \
    { \
        int i_ = tid; \
        int r_ = i_ >> 2, c8_ = (i_ & 3) * 8; \
        uint32_t d_ = base_ + 20480 + r_ * 80 + c8_ * 2; \
        CPA16(d_,        g_Zhi + ((size_t)b * PP + n0 + r_) * CC + (k0) + c8_); \
        CPA16(d_ + 5120, g_Zlo + ((size_t)b * PP + n0 + r_) * CC + (k0) + c8_); \
    } } while (0)

    G2_FILL(0, 0);
    CPA_COMMIT();

    const int NIT = CC / 32;   // 8
    #pragma unroll 1
    for (int it = 0; it < NIT; it++) {
        if (it + 1 < NIT) G2_FILL((it + 1) & 1, (it + 1) * 32);
        CPA_COMMIT();
        CPA_WAIT1();
        __syncthreads();

        const uint32_t stb = sb + (it & 1) * STAGE;
        #pragma unroll
        for (int kk = 0; kk < 2; kk++) {
            const int kb0 = kk * 16;
            uint32_t ah[4][4], al[4][4], bh[4], bl[4];
            #pragma unroll
            for (int mt = 0; mt < 4; mt++) {
                uint32_t aaddr = stb + ((wm * 64 + mt * 16 + (lane & 15)) * ROWE
                                        + kb0 + ((lane >> 4) << 3)) * 2;
                LDSM4(ah[mt][0], ah[mt][1], ah[mt][2], ah[mt][3], aaddr);
                LDSM4(al[mt][0], al[mt][1], al[mt][2], al[mt][3], aaddr + 10240);
            }
            {
                uint32_t baddr = stb + 20480
                    + ((wn * 16 + ((lane >> 4) << 3) + (lane & 7)) * ROWE
                       + kb0 + (((lane >> 3) & 1) << 3)) * 2;
                LDSM4(bh[0], bh[1], bh[2], bh[3], baddr);
                LDSM4(bl[0], bl[1], bl[2], bl[3], baddr + 5120);
            }
            #pragma unroll
            for (int mt = 0; mt < 4; mt++)
                #pragma unroll
                for (int nt = 0; nt < 2; nt++) {
                    MMA_BF16(acc[mt][nt], ah[mt][0], ah[mt][1], ah[mt][2], ah[mt][3],
                             bh[nt * 2], bh[nt * 2 + 1]);
                    MMA_BF16(acc[mt][nt], al[mt][0], al[mt][1], al[mt][2], al[mt][3],
                             bh[nt * 2], bh[nt * 2 + 1]);
                    MMA_BF16(acc[mt][nt], ah[mt][0], ah[mt][1], ah[mt][2], ah[mt][3],
                             bl[nt * 2], bl[nt * 2 + 1]);
                }
        }
        __syncthreads();
    }

    // dense epilogue: BN(axis=d) + ReLU -> R[b][d][p], coalesced float2
    const float inv = rsqrtf(1.0f + 1e-5f);
    #pragma unroll
    for (int mt = 0; mt < 4; mt++) {
        int row0 = m0 + wm * 64 + mt * 16 + grp;   // d
        int row1 = row0 + 8;
        float s0 = inv * gw[row0], t0 = bw[row0];
        float s1 = inv * gw[row1], t1 = bw[row1];
        #pragma unroll
        for (int nt = 0; nt < 2; nt++) {
            int col = n0 + wn * 16 + nt * 8 + qid * 2;   // p
            float2 v0, v1;
            v0.x = fmaxf(fmaf(acc[mt][nt][0], s0, t0), 0.0f);
            v0.y = fmaxf(fmaf(acc[mt][nt][1], s0, t0), 0.0f);
            v1.x = fmaxf(fmaf(acc[mt][nt][2], s1, t1), 0.0f);
            v1.y = fmaxf(fmaf(acc[mt][nt][3], s1, t1), 0.0f);
            *(float2*)(g_R + ((size_t)b * CC + row0) * PP + col) = v0;
            *(float2*)(g_R + ((size_t)b * CC + row1) * PP + col) = v1;
        }
    }
#undef G2_FILL
}

// ---------------- fuse_out: out = inv<0 ? x : R (single dense pass) -
// grid (HWN/256, BB), 256 threads; each block: 256-hw chunk, all 256 c
__global__ __launch_bounds__(256) void fuse_out_kernel(
    const float* __restrict__ x, float* __restrict__ out)
{
    __shared__ int sinv[256];
    const int b = blockIdx.y, hw0 = blockIdx.x * 256;
    const int tid = threadIdx.x;
    sinv[tid] = g_inv[b * HWN + hw0 + tid];
    __syncthreads();

    const float4* X4 = (const float4*)x;
    float4* O4 = (float4*)out;
    const float* Rb = g_R + (size_t)b * CC * PP;

    // 256 c rows x 64 float4 per row = 16384 float4 / block
    #pragma unroll 4
    for (int i = tid; i < 16384; i += 256) {
        int c = i >> 6, f = i & 63;
        size_t gi = (((size_t)b * CC + c) * HWN + hw0) / 4 + f;
        float4 v = X4[gi];
        const float* Rc = Rb + (size_t)c * PP;
        int p0 = sinv[f * 4 + 0];
        int p1 = sinv[f * 4 + 1];
        int p2 = sinv[f * 4 + 2];
        int p3 = sinv[f * 4 + 3];
        if (p0 >= 0) v.x = Rc[p0];
        if (p1 >= 0) v.y = Rc[p1];
        if (p2 >= 0) v.z = Rc[p2];
        if (p3 >= 0) v.w = Rc[p3];
        O4[gi] = v;
    }
}

// ---------------------------------------------------------------
extern "C" void kernel_launch(void* const* d_in, const int* in_sizes, int n_in,
                              void* d_out, int out_size)
{
    const float* x    = (const float*)d_in[0];
    const float* edge = (const float*)d_in[1];
    const float* wadj = (const float*)d_in[2];
    const float* ga   = (const float*)d_in[3];
    const float* be   = (const float*)d_in[4];
    const float* wwg  = (const float*)d_in[5];
    const float* gw   = (const float*)d_in[6];
    const float* bw   = (const float*)d_in[7];
    float* out = (float*)d_out;

    cudaFuncSetAttribute(prep_kernel, cudaFuncAttributeMaxDynamicSharedMemorySize, 65536);
    cudaFuncSetAttribute(gemm1_mma,   cudaFuncAttributeMaxDynamicSharedMemorySize, 2 * STAGE);
    cudaFuncSetAttribute(gemm2_mma,   cudaFuncAttributeMaxDynamicSharedMemorySize, 2 * STAGE);

    // fused: topk + inv map (blocks 0-3) + W splits (4-131)
    prep_kernel<<<132, 1024, 65536>>>(edge, wadj, wwg);

    // gather (needs idx)
    {
        dim3 g(PP / 64, CC / 64, BB);   // (32, 4, 4)
        gather_kernel<<<g, 256>>>(x);
    }

    // GEMM1 + BN + ReLU + residual
    {
        dim3 g(CC / 64, PP / 128, BB);  // (4, 16, 4)
        gemm1_mma<<<g, 256, 2 * STAGE>>>(ga, be);
    }
    // GEMM2 + BN + ReLU -> dense R
    {
        dim3 g(PP / 64, CC / 128, BB);  // (32, 2, 4)
        gemm2_mma<<<g, 256, 2 * STAGE>>>(gw, bw);
    }
    // final fused copy/scatter: out = inv<0 ? x : R
    {
        dim3 g(HWN / 256, BB);          // (64, 4)
        fuse_out_kernel<<<g, 256>>>(x, out);
    }
}

// round 9
// speedup vs baseline: 1.0207x; 1.0207x over previous
#include <cuda_runtime.h>
#include <cuda_bf16.h>
#include <cstdint>

#define BB 4
#define CC 256
#define HWN 16384
#define PP 2048
#define THRV 0.8f

// ---------------- scratch (no allocations allowed) ----------------
__device__ __nv_bfloat16 g_Whi[PP * PP];          // Wadj bf16 hi [o][p]
__device__ __nv_bfloat16 g_Wlo[PP * PP];          // Wadj bf16 lo
__device__ __nv_bfloat16 g_Gthi[BB * CC * PP];    // G^T bf16 hi [b][c][p]
__device__ __nv_bfloat16 g_Gtlo[BB * CC * PP];
__device__ float         g_Gf[BB * PP * CC];      // G fp32 [b][p][c] (residual)
__device__ __nv_bfloat16 g_Zhi[BB * PP * CC];     // stage-1 out bf16 hi [b][p][c]
__device__ __nv_bfloat16 g_Zlo[BB * PP * CC];
__device__ __nv_bfloat16 g_WGhi[CC * CC];         // Wwg bf16 hi [d][c]
__device__ __nv_bfloat16 g_WGlo[CC * CC];
__device__ float         g_R[BB * CC * PP];       // dense stage-2 out [b][d][p]
__device__ int           g_idx[BB * PP];          // topk indices

// ---------------- PTX helpers (baseline ISA: sm_80+) ---------------
__device__ __forceinline__ uint32_t smem_u32(const void* p) {
    uint32_t a;
    asm("{ .reg .u64 t; cvta.to.shared.u64 t, %1; cvt.u32.u64 %0, t; }" : "=r"(a) : "l"(p));
    return a;
}
#define CPA16(dst_u32, src_ptr) \
    asm volatile("cp.async.cg.shared.global [%0], [%1], 16;" :: "r"(dst_u32), "l"(src_ptr) : "memory")
#define CPA_COMMIT() asm volatile("cp.async.commit_group;" ::: "memory")
#define CPA_WAIT2()  asm volatile("cp.async.wait_group 2;" ::: "memory")

#define MMA_BF16(c, a0, a1, a2, a3, b0, b1) \
    asm volatile("mma.sync.aligned.m16n8k16.row.col.f32.bf16.bf16.f32 " \
        "{%0,%1,%2,%3}, {%4,%5,%6,%7}, {%8,%9}, {%0,%1,%2,%3};" \
        : "+f"((c)[0]), "+f"((c)[1]), "+f"((c)[2]), "+f"((c)[3]) \
        : "r"(a0), "r"(a1), "r"(a2), "r"(a3), "r"(b0), "r"(b1))

#define LDSM4(r0, r1, r2, r3, addr) \
    asm volatile("ldmatrix.sync.aligned.m8n8.x4.shared.b16 {%0,%1,%2,%3}, [%4];" \
        : "=r"(r0), "=r"(r1), "=r"(r2), "=r"(r3) : "r"(addr))

__device__ __forceinline__ uint32_t pack_hi2(float a, float b) {
    __nv_bfloat162 t = __floats2bfloat162_rn(a, b);
    return *(uint32_t*)&t;
}

// ---------------- fused prep: topk + W splits + out=x copy ----------
// blocks 0..3      : per-batch top-2048 (compact + bitonic)
// blocks 4..67     : Wadj bf16 hi/lo split (+ Wwg split)
// blocks 68..195   : copy out = x (float4)
__global__ __launch_bounds__(1024) void prep_kernel(
    const float* __restrict__ edge, const float* __restrict__ x,
    const float* __restrict__ wadj, const float* __restrict__ wwg,
    float* __restrict__ out)
{
    const int bid = blockIdx.x, tid = threadIdx.x;

    if (bid < 4) {                                // ---- topk ----
        extern __shared__ unsigned long long keys[];   // 8192 max
        __shared__ int cnt;
        const int b = bid;
        const float* e = edge + b * HWN;
        if (tid == 0) cnt = 0;
        __syncthreads();
        for (int i = tid; i < HWN; i += 1024) {
            float v = e[i];
            if (v >= THRV) {
                int pos = atomicAdd(&cnt, 1);
                if (pos < 8192)
                    keys[pos] = ((unsigned long long)__float_as_uint(v) << 32) | (unsigned int)(~i);
            }
        }
        __syncthreads();
        int c = min(cnt, 8192);
        int n = (c <= 4096) ? 4096 : 8192;
        for (int i = c + tid; i < n; i += 1024) keys[i] = 0ull;
        __syncthreads();
        for (int k = 2; k <= n; k <<= 1) {
            for (int j = k >> 1; j > 0; j >>= 1) {
                for (int i = tid; i < n; i += 1024) {
                    int ixj = i ^ j;
                    if (ixj > i) {
                        unsigned long long a = keys[i], cc2 = keys[ixj];
                        bool up = (i & k) == 0;
                        if (up ? (a < cc2) : (a > cc2)) { keys[i] = cc2; keys[ixj] = a; }
                    }
                }
                __syncthreads();
            }
        }
        for (int p = tid; p < PP; p += 1024)
            g_idx[b * PP + p] = (int)(~(unsigned int)(keys[p] & 0xFFFFFFFFu));
    } else if (bid < 68) {                        // ---- W splits ----
        const int gt = (bid - 4) * 1024 + tid;    // 65536 threads
        const float4* W4 = (const float4*)wadj;   // 1048576 float4
        for (int i = gt; i < PP * PP / 4; i += 64 * 1024) {
            float4 v = W4[i];
            __nv_bfloat16 h0 = __float2bfloat16_rn(v.x), h1 = __float2bfloat16_rn(v.y);
            __nv_bfloat16 h2 = __float2bfloat16_rn(v.z), h3 = __float2bfloat16_rn(v.w);
            uint2 hp, lp;
            hp.x = pack_hi2(v.x, v.y); hp.y = pack_hi2(v.z, v.w);
            lp.x = pack_hi2(v.x - __bfloat162float(h0), v.y - __bfloat162float(h1));
            lp.y = pack_hi2(v.z - __bfloat162float(h2), v.w - __bfloat162float(h3));
            *(uint2*)(g_Whi + (size_t)i * 4) = hp;
            *(uint2*)(g_Wlo + (size_t)i * 4) = lp;
        }
        const float4* G4 = (const float4*)wwg;    // 16384 float4
        if (gt < CC * CC / 4) {
            float4 v = G4[gt];
            __nv_bfloat16 h0 = __float2bfloat16_rn(v.x), h1 = __float2bfloat16_rn(v.y);
            __nv_bfloat16 h2 = __float2bfloat16_rn(v.z), h3 = __float2bfloat16_rn(v.w);
            uint2 hp, lp;
            hp.x = pack_hi2(v.x, v.y); hp.y = pack_hi2(v.z, v.w);
            lp.x = pack_hi2(v.x - __bfloat162float(h0), v.y - __bfloat162float(h1));
            lp.y = pack_hi2(v.z - __bfloat162float(h2), v.w - __bfloat162float(h3));
            *(uint2*)(g_WGhi + (size_t)gt * 4) = hp;
            *(uint2*)(g_WGlo + (size_t)gt * 4) = lp;
        }
    } else {                                      // ---- out = x ----
        const int gt = (bid - 68) * 1024 + tid;   // 131072 threads
        const float4* X4 = (const float4*)x;
        float4* O4 = (float4*)out;
        const int NT = BB * CC * HWN / 4;         // 4194304
        for (int i = gt; i < NT; i += 128 * 1024)
            O4[i] = X4[i];
    }
}

// ---------------- gather: x -> Gt bf16 hi/lo [c][p] + Gf fp32 [p][c]
__global__ __launch_bounds__(256) void gather_kernel(const float* __restrict__ x)
{
    __shared__ float tile[64][65];
    __shared__ int jj[64];
    const int p0 = blockIdx.x * 64, c0 = blockIdx.y * 64, b = blockIdx.z;
    const int tid = threadIdx.x;
    if (tid < 64) jj[tid] = g_idx[b * PP + p0 + tid];
    __syncthreads();

    #pragma unroll
    for (int e = tid; e < 64 * 64; e += 256) {
        int pc = e & 63, cl = e >> 6;
        tile[pc][cl] = x[((size_t)b * CC + c0 + cl) * HWN + jj[pc]];
    }
    __syncthreads();

    #pragma unroll
    for (int e = tid; e < 64 * 64; e += 256) {
        int cl = e >> 6, pc = e & 63;
        float v = tile[pc][cl];
        __nv_bfloat16 h = __float2bfloat16_rn(v);
        size_t o = ((size_t)b * CC + c0 + cl) * PP + p0 + pc;
        g_Gthi[o] = h;
        g_Gtlo[o] = __float2bfloat16_rn(v - __bfloat162float(h));
    }
    #pragma unroll
    for (int e = tid; e < 64 * 64; e += 256) {
        int pc = e >> 6, cl = e & 63;
        g_Gf[((size_t)b * PP + p0 + pc) * CC + c0 + cl] = tile[pc][cl];
    }
}

// ---------------- mma.sync GEMM geometry ---------------------------
// CTA 128(M) x 64(N), BK=32, 256 thr, warps 2(m) x 4(n), warp 64x16.
// smem stage: Ah/Al [128][40], Bh/Bl [64][40] bf16; 80B padded rows.
// 3 stages x 30720 B = 92160 B dynamic smem.
#define STAGE 30720
#define ROWE  40
#define NST   3

// ---------------- GEMM1: Z = relu(BN(W @ G)) + G --------------------
__global__ __launch_bounds__(256, 2) void gemm1_mma(
    const float* __restrict__ ga, const float* __restrict__ be)
{
    extern __shared__ __align__(16) char sm[];
    const uint32_t sb = smem_u32(sm);
    const int tid = threadIdx.x;
    const int b = blockIdx.z, m0 = blockIdx.y * 128, n0 = blockIdx.x * 64;
    const int lane = tid & 31, warp = tid >> 5;
    const int grp = lane >> 2, qid = lane & 3;
    const int wm = warp >> 2, wn = warp & 3;

    float acc[4][2][4];
    #pragma unroll
    for (int i = 0; i < 4; i++)
        #pragma unroll
        for (int j = 0; j < 2; j++)
            #pragma unroll
            for (int r = 0; r < 4; r++) acc[i][j][r] = 0.0f;

#define G1_FILL(st, k0) do { \
    uint32_t base_ = sb + (st) * STAGE; \
    for (int i_ = tid; i_ < 512; i_ += 256) { \
        int r_ = i_ >> 2, c8_ = (i_ & 3) * 8; \
        uint32_t d_ = base_ + r_ * 80 + c8_ * 2; \
        CPA16(d_,         g_Whi + (size_t)(m0 + r_) * PP + (k0) + c8_); \
        CPA16(d_ + 10240, g_Wlo + (size_t)(m0 + r_) * PP + (k0) + c8_); \
    } \
    { \
        int i_ = tid; \
        int r_ = i_ >> 2, c8_ = (i_ & 3) * 8; \
        uint32_t d_ = base_ + 20480 + r_ * 80 + c8_ * 2; \
        CPA16(d_,        g_Gthi + ((size_t)b * CC + n0 + r_) * PP + (k0) + c8_); \
        CPA16(d_ + 5120, g_Gtlo + ((size_t)b * CC + n0 + r_) * PP + (k0) + c8_); \
    } } while (0)

    const int NIT = PP / 32;   // 64
    G1_FILL(0, 0);  CPA_COMMIT();
    G1_FILL(1, 32); CPA_COMMIT();

    #pragma unroll 1
    for (int it = 0; it < NIT; it++) {
        int st = it % NST;
        if (it + 2 < NIT) G1_FILL((it + 2) % NST, (it + 2) * 32);
        CPA_COMMIT();
        CPA_WAIT2();
        __syncthreads();

        const uint32_t stb = sb + st * STAGE;
        #pragma unroll
        for (int kk = 0; kk < 2; kk++) {
            const int kb0 = kk * 16;
            uint32_t ah[4][4], al[4][4], bh[4], bl[4];
            #pragma unroll
            for (int mt = 0; mt < 4; mt++) {
                uint32_t aaddr = stb + ((wm * 64 + mt * 16 + (lane & 15)) * ROWE
                                        + kb0 + ((lane >> 4) << 3)) * 2;
                LDSM4(ah[mt][0], ah[mt][1], ah[mt][2], ah[mt][3], aaddr);
                LDSM4(al[mt][0], al[mt][1], al[mt][2], al[mt][3], aaddr + 10240);
            }
            {
                uint32_t baddr = stb + 20480
                    + ((wn * 16 + ((lane >> 4) << 3) + (lane & 7)) * ROWE
                       + kb0 + (((lane >> 3) & 1) << 3)) * 2;
                LDSM4(bh[0], bh[1], bh[2], bh[3], baddr);
                LDSM4(bl[0], bl[1], bl[2], bl[3], baddr + 5120);
            }
            #pragma unroll
            for (int mt = 0; mt < 4; mt++)
                #pragma unroll
                for (int nt = 0; nt < 2; nt++) {
                    MMA_BF16(acc[mt][nt], ah[mt][0], ah[mt][1], ah[mt][2], ah[mt][3],
                             bh[nt * 2], bh[nt * 2 + 1]);
                    MMA_BF16(acc[mt][nt], al[mt][0], al[mt][1], al[mt][2], al[mt][3],
                             bh[nt * 2], bh[nt * 2 + 1]);
                    MMA_BF16(acc[mt][nt], ah[mt][0], ah[mt][1], ah[mt][2], ah[mt][3],
                             bl[nt * 2], bl[nt * 2 + 1]);
                }
        }
        __syncthreads();
    }

    const float inv = rsqrtf(1.0f + 1e-5f);
    #pragma unroll
    for (int mt = 0; mt < 4; mt++) {
        int row0 = m0 + wm * 64 + mt * 16 + grp;
        int row1 = row0 + 8;
        float s0 = inv * ga[row0], t0 = be[row0];
        float s1 = inv * ga[row1], t1 = be[row1];
        #pragma unroll
        for (int nt = 0; nt < 2; nt++) {
            int col = n0 + wn * 16 + nt * 8 + qid * 2;
            size_t o0 = ((size_t)b * PP + row0) * CC + col;
            size_t o1 = ((size_t)b * PP + row1) * CC + col;
            float2 gf0 = *(const float2*)(g_Gf + o0);
            float2 gf1 = *(const float2*)(g_Gf + o1);
            float v00 = fmaxf(fmaf(acc[mt][nt][0], s0, t0), 0.0f) + gf0.x;
            float v01 = fmaxf(fmaf(acc[mt][nt][1], s0, t0), 0.0f) + gf0.y;
            float v10 = fmaxf(fmaf(acc[mt][nt][2], s1, t1), 0.0f) + gf1.x;
            float v11 = fmaxf(fmaf(acc[mt][nt][3], s1, t1), 0.0f) + gf1.y;
            __nv_bfloat162 h0 = __floats2bfloat162_rn(v00, v01);
            __nv_bfloat162 h1 = __floats2bfloat162_rn(v10, v11);
            *(uint32_t*)(g_Zhi + o0) = *(uint32_t*)&h0;
            *(uint32_t*)(g_Zhi + o1) = *(uint32_t*)&h1;
            __nv_bfloat162 l0 = __floats2bfloat162_rn(v00 - __bfloat162float(h0.x),
                                                      v01 - __bfloat162float(h0.y));
            __nv_bfloat162 l1 = __floats2bfloat162_rn(v10 - __bfloat162float(h1.x),
                                                      v11 - __bfloat162float(h1.y));
            *(uint32_t*)(g_Zlo + o0) = *(uint32_t*)&l0;
            *(uint32_t*)(g_Zlo + o1) = *(uint32_t*)&l1;
        }
    }
#undef G1_FILL
}

// ---------------- GEMM2: R[b][d][p] = relu(BN(WG @ Z^T)), DENSE -----
// M = d (256), N = p (2048), K = c (256)
__global__ __launch_bounds__(256, 2) void gemm2_mma(
    const float* __restrict__ gw, const float* __restrict__ bw)
{
    extern __shared__ __align__(16) char sm[];
    const uint32_t sb = smem_u32(sm);
    const int tid = threadIdx.x;
    const int b = blockIdx.z, m0 = blockIdx.y * 128, n0 = blockIdx.x * 64;
    const int lane = tid & 31, warp = tid >> 5;
    const int grp = lane >> 2, qid = lane & 3;
    const int wm = warp >> 2, wn = warp & 3;

    float acc[4][2][4];
    #pragma unroll
    for (int i = 0; i < 4; i++)
        #pragma unroll
        for (int j = 0; j < 2; j++)
            #pragma unroll
            for (int r = 0; r < 4; r++) acc[i][j][r] = 0.0f;

#define G2_FILL(st, k0) do { \
    uint32_t base_ = sb + (st) * STAGE; \
    for (int i_ = tid; i_ < 512; i_ += 256) { \
        int r_ = i_ >> 2, c8_ = (i_ & 3) * 8; \
        uint32_t d_ = base_ + r_ * 80 + c8_ * 2; \
        CPA16(d_,         g_WGhi + (size_t)(m0 + r_) * CC + (k0) + c8_); \
        CPA16(d_ + 10240, g_WGlo + (size_t)(m0 + r_) * CC + (k0) + c8_); \
    } \
    { \
        int i_ = tid; \
        int r_ = i_ >> 2, c8_ = (i_ & 3) * 8; \
        uint32_t d_ = base_ + 20480 + r_ * 80 + c8_ * 2; \
        CPA16(d_,        g_Zhi + ((size_t)b * PP + n0 + r_) * CC + (k0) + c8_); \
        CPA16(d_ + 5120, g_Zlo + ((size_t)b * PP + n0 + r_) * CC + (k0) + c8_); \
    } } while (0)

    const int NIT = CC / 32;   // 8
    G2_FILL(0, 0);  CPA_COMMIT();
    G2_FILL(1, 32); CPA_COMMIT();

    #pragma unroll 1
    for (int it = 0; it < NIT; it++) {
        int st = it % NST;
        if (it + 2 < NIT) G2_FILL((it + 2) % NST, (it + 2) * 32);
        CPA_COMMIT();
        CPA_WAIT2();
        __syncthreads();

        const uint32_t stb = sb + st * STAGE;
        #pragma unroll
        for (int kk = 0; kk < 2; kk++) {
            const int kb0 = kk * 16;
            uint32_t ah[4][4], al[4][4], bh[4], bl[4];
            #pragma unroll
            for (int mt = 0; mt < 4; mt++) {
                uint32_t aaddr = stb + ((wm * 64 + mt * 16 + (lane & 15)) * ROWE
                                        + kb0 + ((lane >> 4) << 3)) * 2;
                LDSM4(ah[mt][0], ah[mt][1], ah[mt][2], ah[mt][3], aaddr);
                LDSM4(al[mt][0], al[mt][1], al[mt][2], al[mt][3], aaddr + 10240);
            }
            {
                uint32_t baddr = stb + 20480
                    + ((wn * 16 + ((lane >> 4) << 3) + (lane & 7)) * ROWE
                       + kb0 + (((lane >> 3) & 1) << 3)) * 2;
                LDSM4(bh[0], bh[1], bh[2], bh[3], baddr);
                LDSM4(bl[0], bl[1], bl[2], bl[3], baddr + 5120);
            }
            #pragma unroll
            for (int mt = 0; mt < 4; mt++)
                #pragma unroll
                for (int nt = 0; nt < 2; nt++) {
                    MMA_BF16(acc[mt][nt], ah[mt][0], ah[mt][1], ah[mt][2], ah[mt][3],
                             bh[nt * 2], bh[nt * 2 + 1]);
                    MMA_BF16(acc[mt][nt], al[mt][0], al[mt][1], al[mt][2], al[mt][3],
                             bh[nt * 2], bh[nt * 2 + 1]);
                    MMA_BF16(acc[mt][nt], ah[mt][0], ah[mt][1], ah[mt][2], ah[mt][3],
                             bl[nt * 2], bl[nt * 2 + 1]);
                }
        }
        __syncthreads();
    }

    // dense epilogue: BN(axis=d) + ReLU -> R[b][d][p], coalesced float2
    const float inv = rsqrtf(1.0f + 1e-5f);
    #pragma unroll
    for (int mt = 0; mt < 4; mt++) {
        int row0 = m0 + wm * 64 + mt * 16 + grp;   // d
        int row1 = row0 + 8;
        float s0 = inv * gw[row0], t0 = bw[row0];
        float s1 = inv * gw[row1], t1 = bw[row1];
        #pragma unroll
        for (int nt = 0; nt < 2; nt++) {
            int col = n0 + wn * 16 + nt * 8 + qid * 2;   // p
            float2 v0, v1;
            v0.x = fmaxf(fmaf(acc[mt][nt][0], s0, t0), 0.0f);
            v0.y = fmaxf(fmaf(acc[mt][nt][1], s0, t0), 0.0f);
            v1.x = fmaxf(fmaf(acc[mt][nt][2], s1, t1), 0.0f);
            v1.y = fmaxf(fmaf(acc[mt][nt][3], s1, t1), 0.0f);
            *(float2*)(g_R + ((size_t)b * CC + row0) * PP + col) = v0;
            *(float2*)(g_R + ((size_t)b * CC + row1) * PP + col) = v1;
        }
    }
#undef G2_FILL
}

// ---------------- scatter: out[b][d][idx[p]] = R[b][d][p] -----------
// grid (PP/256, CC/8, BB), 256 thr; coalesced R reads, scattered writes
__global__ __launch_bounds__(256) void scatter_kernel(float* __restrict__ out)
{
    __shared__ int jj[256];
    const int p0 = blockIdx.x * 256, d0 = blockIdx.y * 8, b = blockIdx.z;
    const int tid = threadIdx.x;
    jj[tid] = g_idx[b * PP + p0 + tid];
    __syncthreads();

    const int j = jj[tid];
    const float* Rb = g_R + ((size_t)b * CC + d0) * PP + p0 + tid;
    float* ob = out + ((size_t)b * CC + d0) * HWN + j;
    #pragma unroll
    for (int k = 0; k < 8; k++)
        ob[(size_t)k * HWN] = Rb[(size_t)k * PP];
}

// ---------------------------------------------------------------
extern "C" void kernel_launch(void* const* d_in, const int* in_sizes, int n_in,
                              void* d_out, int out_size)
{
    const float* x    = (const float*)d_in[0];
    const float* edge = (const float*)d_in[1];
    const float* wadj = (const float*)d_in[2];
    const float* ga   = (const float*)d_in[3];
    const float* be   = (const float*)d_in[4];
    const float* wwg  = (const float*)d_in[5];
    const float* gw   = (const float*)d_in[6];
    const float* bw   = (const float*)d_in[7];
    float* out = (float*)d_out;

    cudaFuncSetAttribute(prep_kernel, cudaFuncAttributeMaxDynamicSharedMemorySize, 65536);
    cudaFuncSetAttribute(gemm1_mma,   cudaFuncAttributeMaxDynamicSharedMemorySize, NST * STAGE);
    cudaFuncSetAttribute(gemm2_mma,   cudaFuncAttributeMaxDynamicSharedMemorySize, NST * STAGE);

    // fused: topk (0-3) + W splits (4-67) + out=x copy (68-195)
    prep_kernel<<<196, 1024, 65536>>>(edge, x, wadj, wwg, out);

    // gather (needs idx)
    {
        dim3 g(PP / 64, CC / 64, BB);   // (32, 4, 4)
        gather_kernel<<<g, 256>>>(x);
    }

    // GEMM1 + BN + ReLU + residual
    {
        dim3 g(CC / 64, PP / 128, BB);  // (4, 16, 4)
        gemm1_mma<<<g, 256, NST * STAGE>>>(ga, be);
    }
    // GEMM2 + BN + ReLU -> dense R
    {
        dim3 g(PP / 64, CC / 128, BB);  // (32, 2, 4)
        gemm2_mma<<<g, 256, NST * STAGE>>>(gw, bw);
    }
    // scatter R into out (out already = x from prep)
    {
        dim3 g(PP / 256, CC / 8, BB);   // (8, 32, 4)
        scatter_kernel<<<g, 256>>>(out);
    }
}

// round 10
// speedup vs baseline: 1.4211x; 1.3922x over previous
#include <cuda_runtime.h>
#include <cuda_bf16.h>
#include <cstdint>

#define BB 4
#define CC 256
#define HWN 16384
#define PP 2048
#define THRV 0.8f

// ---------------- scratch (no allocations allowed) ----------------
__device__ __nv_bfloat16 g_Whi[PP * PP];          // Wadj bf16 hi [o][p]
__device__ __nv_bfloat16 g_Wlo[PP * PP];          // Wadj bf16 lo
__device__ __nv_bfloat16 g_Gthi[BB * CC * PP];    // G^T bf16 hi [b][c][p]
__device__ __nv_bfloat16 g_Gtlo[BB * CC * PP];
__device__ float         g_Gf[BB * PP * CC];      // G fp32 [b][p][c] (residual)
__device__ __nv_bfloat16 g_Zhi[BB * PP * CC];     // stage-1 out bf16 hi [b][p][c]
__device__ __nv_bfloat16 g_Zlo[BB * PP * CC];
__device__ __nv_bfloat16 g_WGhi[CC * CC];         // Wwg bf16 hi [d][c]
__device__ __nv_bfloat16 g_WGlo[CC * CC];
__device__ float         g_R[BB * CC * PP];       // dense stage-2 out [b][d][p]
__device__ int           g_idx[BB * PP];          // topk indices

// ---------------- PTX helpers (baseline ISA: sm_80+) ---------------
__device__ __forceinline__ uint32_t smem_u32(const void* p) {
    uint32_t a;
    asm("{ .reg .u64 t; cvta.to.shared.u64 t, %1; cvt.u32.u64 %0, t; }" : "=r"(a) : "l"(p));
    return a;
}
#define CPA16(dst_u32, src_ptr) \
    asm volatile("cp.async.cg.shared.global [%0], [%1], 16;" :: "r"(dst_u32), "l"(src_ptr) : "memory")
#define CPA_COMMIT() asm volatile("cp.async.commit_group;" ::: "memory")
#define CPA_WAIT1()  asm volatile("cp.async.wait_group 1;" ::: "memory")

#define MMA_BF16(c, a0, a1, a2, a3, b0, b1) \
    asm volatile("mma.sync.aligned.m16n8k16.row.col.f32.bf16.bf16.f32 " \
        "{%0,%1,%2,%3}, {%4,%5,%6,%7}, {%8,%9}, {%0,%1,%2,%3};" \
        : "+f"((c)[0]), "+f"((c)[1]), "+f"((c)[2]), "+f"((c)[3]) \
        : "r"(a0), "r"(a1), "r"(a2), "r"(a3), "r"(b0), "r"(b1))

#define LDSM4(r0, r1, r2, r3, addr) \
    asm volatile("ldmatrix.sync.aligned.m8n8.x4.shared.b16 {%0,%1,%2,%3}, [%4];" \
        : "=r"(r0), "=r"(r1), "=r"(r2), "=r"(r3) : "r"(addr))

__device__ __forceinline__ uint32_t pack_hi2(float a, float b) {
    __nv_bfloat162 t = __floats2bfloat162_rn(a, b);
    return *(uint32_t*)&t;
}

// ---------------- fused prep: topk + W splits + out=x copy ----------
// blocks 0..3      : per-batch top-2048 (compact + bitonic)
// blocks 4..67     : Wadj bf16 hi/lo split (+ Wwg split)
// blocks 68..195   : copy out = x (float4)
__global__ __launch_bounds__(1024) void prep_kernel(
    const float* __restrict__ edge, const float* __restrict__ x,
    const float* __restrict__ wadj, const float* __restrict__ wwg,
    float* __restrict__ out)
{
    const int bid = blockIdx.x, tid = threadIdx.x;

    if (bid < 4) {                                // ---- topk ----
        extern __shared__ unsigned long long keys[];   // 8192 max
        __shared__ int cnt;
        const int b = bid;
        const float* e = edge + b * HWN;
        if (tid == 0) cnt = 0;
        __syncthreads();
        for (int i = tid; i < HWN; i += 1024) {
            float v = e[i];
            if (v >= THRV) {
                int pos = atomicAdd(&cnt, 1);
                if (pos < 8192)
                    keys[pos] = ((unsigned long long)__float_as_uint(v) << 32) | (unsigned int)(~i);
            }
        }
        __syncthreads();
        int c = min(cnt, 8192);
        int n = (c <= 4096) ? 4096 : 8192;
        for (int i = c + tid; i < n; i += 1024) keys[i] = 0ull;
        __syncthreads();
        for (int k = 2; k <= n; k <<= 1) {
            for (int j = k >> 1; j > 0; j >>= 1) {
                for (int i = tid; i < n; i += 1024) {
                    int ixj = i ^ j;
                    if (ixj > i) {
                        unsigned long long a = keys[i], cc2 = keys[ixj];
                        bool up = (i & k) == 0;
                        if (up ? (a < cc2) : (a > cc2)) { keys[i] = cc2; keys[ixj] = a; }
                    }
                }
                __syncthreads();
            }
        }
        for (int p = tid; p < PP; p += 1024)
            g_idx[b * PP + p] = (int)(~(unsigned int)(keys[p] & 0xFFFFFFFFu));
    } else if (bid < 68) {                        // ---- W splits ----
        const int gt = (bid - 4) * 1024 + tid;    // 65536 threads
        const float4* W4 = (const float4*)wadj;   // 1048576 float4
        for (int i = gt; i < PP * PP / 4; i += 64 * 1024) {
            float4 v = W4[i];
            __nv_bfloat16 h0 = __float2bfloat16_rn(v.x), h1 = __float2bfloat16_rn(v.y);
            __nv_bfloat16 h2 = __float2bfloat16_rn(v.z), h3 = __float2bfloat16_rn(v.w);
            uint2 hp, lp;
            hp.x = pack_hi2(v.x, v.y); hp.y = pack_hi2(v.z, v.w);
            lp.x = pack_hi2(v.x - __bfloat162float(h0), v.y - __bfloat162float(h1));
            lp.y = pack_hi2(v.z - __bfloat162float(h2), v.w - __bfloat162float(h3));
            *(uint2*)(g_Whi + (size_t)i * 4) = hp;
            *(uint2*)(g_Wlo + (size_t)i * 4) = lp;
        }
        const float4* G4 = (const float4*)wwg;    // 16384 float4
        if (gt < CC * CC / 4) {
            float4 v = G4[gt];
            __nv_bfloat16 h0 = __float2bfloat16_rn(v.x), h1 = __float2bfloat16_rn(v.y);
            __nv_bfloat16 h2 = __float2bfloat16_rn(v.z), h3 = __float2bfloat16_rn(v.w);
            uint2 hp, lp;
            hp.x = pack_hi2(v.x, v.y); hp.y = pack_hi2(v.z, v.w);
            lp.x = pack_hi2(v.x - __bfloat162float(h0), v.y - __bfloat162float(h1));
            lp.y = pack_hi2(v.z - __bfloat162float(h2), v.w - __bfloat162float(h3));
            *(uint2*)(g_WGhi + (size_t)gt * 4) = hp;
            *(uint2*)(g_WGlo + (size_t)gt * 4) = lp;
        }
    } else {                                      // ---- out = x ----
        const int gt = (bid - 68) * 1024 + tid;   // 131072 threads
        const float4* X4 = (const float4*)x;
        float4* O4 = (float4*)out;
        const int NT = BB * CC * HWN / 4;         // 4194304
        for (int i = gt; i < NT; i += 128 * 1024)
            O4[i] = X4[i];
    }
}

// ---------------- gather: x -> Gt bf16 hi/lo [c][p] + Gf fp32 [p][c]
__global__ __launch_bounds__(256) void gather_kernel(const float* __restrict__ x)
{
    __shared__ float tile[64][65];
    __shared__ int jj[64];
    const int p0 = blockIdx.x * 64, c0 = blockIdx.y * 64, b = blockIdx.z;
    const int tid = threadIdx.x;
    if (tid < 64) jj[tid] = g_idx[b * PP + p0 + tid];
    __syncthreads();

    #pragma unroll
    for (int e = tid; e < 64 * 64; e += 256) {
        int pc = e & 63, cl = e >> 6;
        tile[pc][cl] = x[((size_t)b * CC + c0 + cl) * HWN + jj[pc]];
    }
    __syncthreads();

    #pragma unroll
    for (int e = tid; e < 64 * 64; e += 256) {
        int cl = e >> 6, pc = e & 63;
        float v = tile[pc][cl];
        __nv_bfloat16 h = __float2bfloat16_rn(v);
        size_t o = ((size_t)b * CC + c0 + cl) * PP + p0 + pc;
        g_Gthi[o] = h;
        g_Gtlo[o] = __float2bfloat16_rn(v - __bfloat162float(h));
    }
    #pragma unroll
    for (int e = tid; e < 64 * 64; e += 256) {
        int pc = e >> 6, cl = e & 63;
        g_Gf[((size_t)b * PP + p0 + pc) * CC + c0 + cl] = tile[pc][cl];
    }
}

// ---------------- mma.sync GEMM geometry ---------------------------
// CTA 128(M) x 64(N), BK=32, 256 thr, warps 2(m) x 4(n), warp 64x16.
// smem stage: Ah/Al [128][40], Bh/Bl [64][40] bf16; 80B padded rows.
// STAGE = 30720 B, 2 stages (61440 B total -> 2 CTAs/SM fits easily).
#define STAGE 30720
#define ROWE  40

// ---------------- GEMM1: Z = relu(BN(W @ G)) + G --------------------
__global__ __launch_bounds__(256, 2) void gemm1_mma(
    const float* __restrict__ ga, const float* __restrict__ be)
{
    extern __shared__ __align__(16) char sm[];
    const uint32_t sb = smem_u32(sm);
    const int tid = threadIdx.x;
    const int b = blockIdx.z, m0 = blockIdx.y * 128, n0 = blockIdx.x * 64;
    const int lane = tid & 31, warp = tid >> 5;
    const int grp = lane >> 2, qid = lane & 3;
    const int wm = warp >> 2, wn = warp & 3;

    float acc[4][2][4];
    #pragma unroll
    for (int i = 0; i < 4; i++)
        #pragma unroll
        for (int j = 0; j < 2; j++)
            #pragma unroll
            for (int r = 0; r < 4; r++) acc[i][j][r] = 0.0f;

#define G1_FILL(st, k0) do { \
    uint32_t base_ = sb + (st) * STAGE; \
    for (int i_ = tid; i_ < 512; i_ += 256) { \
        int r_ = i_ >> 2, c8_ = (i_ & 3) * 8; \
        uint32_t d_ = base_ + r_ * 80 + c8_ * 2; \
        CPA16(d_,         g_Whi + (size_t)(m0 + r_) * PP + (k0) + c8_); \
        CPA16(d_ + 10240, g_Wlo + (size_t)(m0 + r_) * PP + (k0) + c8_); \
    } \
    { \
        int i_ = tid; \
        int r_ = i_ >> 2, c8_ = (i_ & 3) * 8; \
        uint32_t d_ = base_ + 20480 + r_ * 80 + c8_ * 2; \
        CPA16(d_,        g_Gthi + ((size_t)b * CC + n0 + r_) * PP + (k0) + c8_); \
        CPA16(d_ + 5120, g_Gtlo + ((size_t)b * CC + n0 + r_) * PP + (k0) + c8_); \
    } } while (0)

    G1_FILL(0, 0);
    CPA_COMMIT();

    const int NIT = PP / 32;   // 64
    #pragma unroll 1
    for (int it = 0; it < NIT; it++) {
        if (it + 1 < NIT) G1_FILL((it + 1) & 1, (it + 1) * 32);
        CPA_COMMIT();
        CPA_WAIT1();
        __syncthreads();

        const uint32_t stb = sb + (it & 1) * STAGE;
        #pragma unroll
        for (int kk = 0; kk < 2; kk++) {
            const int kb0 = kk * 16;
            uint32_t ah[4][4], al[4][4], bh[4], bl[4];
            #pragma unroll
            for (int mt = 0; mt < 4; mt++) {
                uint32_t aaddr = stb + ((wm * 64 + mt * 16 + (lane & 15)) * ROWE
                                        + kb0 + ((lane >> 4) << 3)) * 2;
                LDSM4(ah[mt][0], ah[mt][1], ah[mt][2], ah[mt][3], aaddr);
                LDSM4(al[mt][0], al[mt][1], al[mt][2], al[mt][3], aaddr + 10240);
            }
            {
                uint32_t baddr = stb + 20480
                    + ((wn * 16 + ((lane >> 4) << 3) + (lane & 7)) * ROWE
                       + kb0 + (((lane >> 3) & 1) << 3)) * 2;
                LDSM4(bh[0], bh[1], bh[2], bh[3], baddr);
                LDSM4(bl[0], bl[1], bl[2], bl[3], baddr + 5120);
            }
            #pragma unroll
            for (int mt = 0; mt < 4; mt++)
                #pragma unroll
                for (int nt = 0; nt < 2; nt++) {
                    MMA_BF16(acc[mt][nt], ah[mt][0], ah[mt][1], ah[mt][2], ah[mt][3],
                             bh[nt * 2], bh[nt * 2 + 1]);
                    MMA_BF16(acc[mt][nt], al[mt][0], al[mt][1], al[mt][2], al[mt][3],
                             bh[nt * 2], bh[nt * 2 + 1]);
                    MMA_BF16(acc[mt][nt], ah[mt][0], ah[mt][1], ah[mt][2], ah[mt][3],
                             bl[nt * 2], bl[nt * 2 + 1]);
                }
        }
        __syncthreads();
    }

    const float inv = rsqrtf(1.0f + 1e-5f);
    #pragma unroll
    for (int mt = 0; mt < 4; mt++) {
        int row0 = m0 + wm * 64 + mt * 16 + grp;
        int row1 = row0 + 8;
        float s0 = inv * ga[row0], t0 = be[row0];
        float s1 = inv * ga[row1], t1 = be[row1];
        #pragma unroll
        for (int nt = 0; nt < 2; nt++) {
            int col = n0 + wn * 16 + nt * 8 + qid * 2;
            size_t o0 = ((size_t)b * PP + row0) * CC + col;
            size_t o1 = ((size_t)b * PP + row1) * CC + col;
            float2 gf0 = *(const float2*)(g_Gf + o0);
            float2 gf1 = *(const float2*)(g_Gf + o1);
            float v00 = fmaxf(fmaf(acc[mt][nt][0], s0, t0), 0.0f) + gf0.x;
            float v01 = fmaxf(fmaf(acc[mt][nt][1], s0, t0), 0.0f) + gf0.y;
            float v10 = fmaxf(fmaf(acc[mt][nt][2], s1, t1), 0.0f) + gf1.x;
            float v11 = fmaxf(fmaf(acc[mt][nt][3], s1, t1), 0.0f) + gf1.y;
            __nv_bfloat162 h0 = __floats2bfloat162_rn(v00, v01);
            __nv_bfloat162 h1 = __floats2bfloat162_rn(v10, v11);
            *(uint32_t*)(g_Zhi + o0) = *(uint32_t*)&h0;
            *(uint32_t*)(g_Zhi + o1) = *(uint32_t*)&h1;
            __nv_bfloat162 l0 = __floats2bfloat162_rn(v00 - __bfloat162float(h0.x),
                                                      v01 - __bfloat162float(h0.y));
            __nv_bfloat162 l1 = __floats2bfloat162_rn(v10 - __bfloat162float(h1.x),
                                                      v11 - __bfloat162float(h1.y));
            *(uint32_t*)(g_Zlo + o0) = *(uint32_t*)&l0;
            *(uint32_t*)(g_Zlo + o1) = *(uint32_t*)&l1;
        }
    }
#undef G1_FILL
}

// ---------------- GEMM2: R[b][d][p] = relu(BN(WG @ Z^T)), DENSE -----
// M = d (256), N = p (2048), K = c (256); 2-stage pipeline (proven 25.5us)
__global__ __launch_bounds__(256, 2) void gemm2_mma(
    const float* __restrict__ gw, const float* __restrict__ bw)
{
    extern __shared__ __align__(16) char sm[];
    const uint32_t sb = smem_u32(sm);
    const int tid = threadIdx.x;
    const int b = blockIdx.z, m0 = blockIdx.y * 128, n0 = blockIdx.x * 64;
    const int lane = tid & 31, warp = tid >> 5;
    const int grp = lane >> 2, qid = lane & 3;
    const int wm = warp >> 2, wn = warp & 3;

    float acc[4][2][4];
    #pragma unroll
    for (int i = 0; i < 4; i++)
        #pragma unroll
        for (int j = 0; j < 2; j++)
            #pragma unroll
            for (int r = 0; r < 4; r++) acc[i][j][r] = 0.0f;

#define G2_FILL(st, k0) do { \
    uint32_t base_ = sb + (st) * STAGE; \
    for (int i_ = tid; i_ < 512; i_ += 256) { \
        int r_ = i_ >> 2, c8_ = (i_ & 3) * 8; \
        uint32_t d_ = base_ + r_ * 80 + c8_ * 2; \
        CPA16(d_,         g_WGhi + (size_t)(m0 + r_) * CC + (k0) + c8_); \
        CPA16(d_ + 10240, g_WGlo + (size_t)(m0 + r_) * CC + (k0) + c8_); \
    } \
    { \
        int i_ = tid; \
        int r_ = i_ >> 2, c8_ = (i_ & 3) * 8; \
        uint32_t d_ = base_ + 20480 + r_ * 80 + c8_ * 2; \
        CPA16(d_,        g_Zhi + ((size_t)b * PP + n0 + r_) * CC + (k0) + c8_); \
        CPA16(d_ + 5120, g_Zlo + ((size_t)b * PP + n0 + r_) * CC + (k0) + c8_); \
    } } while (0)

    G2_FILL(0, 0);
    CPA_COMMIT();

    const int NIT = CC / 32;   // 8
    #pragma unroll 1
    for (int it = 0; it < NIT; it++) {
        if (it + 1 < NIT) G2_FILL((it + 1) & 1, (it + 1) * 32);
        CPA_COMMIT();
        CPA_WAIT1();
        __syncthreads();

        const uint32_t stb = sb + (it & 1) * STAGE;
        #pragma unroll
        for (int kk = 0; kk < 2; kk++) {
            const int kb0 = kk * 16;
            uint32_t ah[4][4], al[4][4], bh[4], bl[4];
            #pragma unroll
            for (int mt = 0; mt < 4; mt++) {
                uint32_t aaddr = stb + ((wm * 64 + mt * 16 + (lane & 15)) * ROWE
                                        + kb0 + ((lane >> 4) << 3)) * 2;
                LDSM4(ah[mt][0], ah[mt][1], ah[mt][2], ah[mt][3], aaddr);
                LDSM4(al[mt][0], al[mt][1], al[mt][2], al[mt][3], aaddr + 10240);
            }
            {
                uint32_t baddr = stb + 20480
                    + ((wn * 16 + ((lane >> 4) << 3) + (lane & 7)) * ROWE
                       + kb0 + (((lane >> 3) & 1) << 3)) * 2;
                LDSM4(bh[0], bh[1], bh[2], bh[3], baddr);
                LDSM4(bl[0], bl[1], bl[2], bl[3], baddr + 5120);
            }
            #pragma unroll
            for (int mt = 0; mt < 4; mt++)
                #pragma unroll
                for (int nt = 0; nt < 2; nt++) {
                    MMA_BF16(acc[mt][nt], ah[mt][0], ah[mt][1], ah[mt][2], ah[mt][3],
                             bh[nt * 2], bh[nt * 2 + 1]);
                    MMA_BF16(acc[mt][nt], al[mt][0], al[mt][1], al[mt][2], al[mt][3],
                             bh[nt * 2], bh[nt * 2 + 1]);
                    MMA_BF16(acc[mt][nt], ah[mt][0], ah[mt][1], ah[mt][2], ah[mt][3],
                             bl[nt * 2], bl[nt * 2 + 1]);
                }
        }
        __syncthreads();
    }

    // dense epilogue: BN(axis=d) + ReLU -> R[b][d][p], coalesced float2
    const float inv = rsqrtf(1.0f + 1e-5f);
    #pragma unroll
    for (int mt = 0; mt < 4; mt++) {
        int row0 = m0 + wm * 64 + mt * 16 + grp;   // d
        int row1 = row0 + 8;
        float s0 = inv * gw[row0], t0 = bw[row0];
        float s1 = inv * gw[row1], t1 = bw[row1];
        #pragma unroll
        for (int nt = 0; nt < 2; nt++) {
            int col = n0 + wn * 16 + nt * 8 + qid * 2;   // p
            float2 v0, v1;
            v0.x = fmaxf(fmaf(acc[mt][nt][0], s0, t0), 0.0f);
            v0.y = fmaxf(fmaf(acc[mt][nt][1], s0, t0), 0.0f);
            v1.x = fmaxf(fmaf(acc[mt][nt][2], s1, t1), 0.0f);
            v1.y = fmaxf(fmaf(acc[mt][nt][3], s1, t1), 0.0f);
            *(float2*)(g_R + ((size_t)b * CC + row0) * PP + col) = v0;
            *(float2*)(g_R + ((size_t)b * CC + row1) * PP + col) = v1;
        }
    }
#undef G2_FILL
}

// ---------------- scatter: out[b][d][idx[p]] = R[b][d][p] -----------
// grid (PP/256, CC/8, BB), 256 thr; coalesced R reads, scattered writes
__global__ __launch_bounds__(256) void scatter_kernel(float* __restrict__ out)
{
    __shared__ int jj[256];
    const int p0 = blockIdx.x * 256, d0 = blockIdx.y * 8, b = blockIdx.z;
    const int tid = threadIdx.x;
    jj[tid] = g_idx[b * PP + p0 + tid];
    __syncthreads();

    const int j = jj[tid];
    const float* Rb = g_R + ((size_t)b * CC + d0) * PP + p0 + tid;
    float* ob = out + ((size_t)b * CC + d0) * HWN + j;
    #pragma unroll
    for (int k = 0; k < 8; k++)
        ob[(size_t)k * HWN] = Rb[(size_t)k * PP];
}

// ---------------------------------------------------------------
extern "C" void kernel_launch(void* const* d_in, const int* in_sizes, int n_in,
                              void* d_out, int out_size)
{
    const float* x    = (const float*)d_in[0];
    const float* edge = (const float*)d_in[1];
    const float* wadj = (const float*)d_in[2];
    const float* ga   = (const float*)d_in[3];
    const float* be   = (const float*)d_in[4];
    const float* wwg  = (const float*)d_in[5];
    const float* gw   = (const float*)d_in[6];
    const float* bw   = (const float*)d_in[7];
    float* out = (float*)d_out;

    cudaFuncSetAttribute(prep_kernel, cudaFuncAttributeMaxDynamicSharedMemorySize, 65536);
    cudaFuncSetAttribute(gemm1_mma,   cudaFuncAttributeMaxDynamicSharedMemorySize, 2 * STAGE);
    cudaFuncSetAttribute(gemm2_mma,   cudaFuncAttributeMaxDynamicSharedMemorySize, 2 * STAGE);

    // fused: topk (0-3) + W splits (4-67) + out=x copy (68-195)
    prep_kernel<<<196, 1024, 65536>>>(edge, x, wadj, wwg, out);

    // gather (needs idx)
    {
        dim3 g(PP / 64, CC / 64, BB);   // (32, 4, 4)
        gather_kernel<<<g, 256>>>(x);
    }

    // GEMM1 + BN + ReLU + residual
    {
        dim3 g(CC / 64, PP / 128, BB);  // (4, 16, 4)
        gemm1_mma<<<g, 256, 2 * STAGE>>>(ga, be);
    }
    // GEMM2 + BN + ReLU -> dense R
    {
        dim3 g(PP / 64, CC / 128, BB);  // (32, 2, 4)
        gemm2_mma<<<g, 256, 2 * STAGE>>>(gw, bw);
    }
    // scatter R into out (out already = x from prep)
    {
        dim3 g(PP / 256, CC / 8, BB);   // (8, 32, 4)
        scatter_kernel<<<g, 256>>>(out);
    }
}

// round 11
// speedup vs baseline: 1.4808x; 1.0420x over previous
#include <cuda_runtime.h>
#include <cuda_bf16.h>
#include <cstdint>

#define BB 4
#define CC 256
#define HWN 16384
#define PP 2048
#define THRV 0.8f

// ---------------- scratch (no allocations allowed) ----------------
__device__ __nv_bfloat16 g_Whi[PP * PP];          // Wadj bf16 hi [o][p]
__device__ __nv_bfloat16 g_Wlo[PP * PP];          // Wadj bf16 lo
__device__ __nv_bfloat16 g_Gthi[BB * CC * PP];    // G^T bf16 hi [b][c][p]
__device__ __nv_bfloat16 g_Gtlo[BB * CC * PP];
__device__ float         g_Gf[BB * PP * CC];      // G fp32 [b][p][c] (residual)
__device__ __nv_bfloat16 g_Zhi[BB * PP * CC];     // stage-1 out bf16 hi [b][p][c]
__device__ __nv_bfloat16 g_Zlo[BB * PP * CC];
__device__ __nv_bfloat16 g_WGhi[CC * CC];         // Wwg bf16 hi [d][c]
__device__ __nv_bfloat16 g_WGlo[CC * CC];
__device__ float         g_R[BB * CC * PP];       // dense stage-2 out [b][d][p]
__device__ int           g_idx[BB * PP];          // topk indices

// ---------------- PTX helpers (baseline ISA: sm_80+) ---------------
__device__ __forceinline__ uint32_t smem_u32(const void* p) {
    uint32_t a;
    asm("{ .reg .u64 t; cvta.to.shared.u64 t, %1; cvt.u32.u64 %0, t; }" : "=r"(a) : "l"(p));
    return a;
}
#define CPA16(dst_u32, src_ptr) \
    asm volatile("cp.async.cg.shared.global [%0], [%1], 16;" :: "r"(dst_u32), "l"(src_ptr) : "memory")
#define CPA_COMMIT() asm volatile("cp.async.commit_group;" ::: "memory")
#define CPA_WAIT1()  asm volatile("cp.async.wait_group 1;" ::: "memory")

#define MMA_BF16(c, a0, a1, a2, a3, b0, b1) \
    asm volatile("mma.sync.aligned.m16n8k16.row.col.f32.bf16.bf16.f32 " \
        "{%0,%1,%2,%3}, {%4,%5,%6,%7}, {%8,%9}, {%0,%1,%2,%3};" \
        : "+f"((c)[0]), "+f"((c)[1]), "+f"((c)[2]), "+f"((c)[3]) \
        : "r"(a0), "r"(a1), "r"(a2), "r"(a3), "r"(b0), "r"(b1))

#define LDSM4(r0, r1, r2, r3, addr) \
    asm volatile("ldmatrix.sync.aligned.m8n8.x4.shared.b16 {%0,%1,%2,%3}, [%4];" \
        : "=r"(r0), "=r"(r1), "=r"(r2), "=r"(r3) : "r"(addr))

__device__ __forceinline__ uint32_t pack_hi2(float a, float b) {
    __nv_bfloat162 t = __floats2bfloat162_rn(a, b);
    return *(uint32_t*)&t;
}

// ---------------- fused prep: topk + W splits + out=x copy ----------
__global__ __launch_bounds__(1024) void prep_kernel(
    const float* __restrict__ edge, const float* __restrict__ x,
    const float* __restrict__ wadj, const float* __restrict__ wwg,
    float* __restrict__ out)
{
    const int bid = blockIdx.x, tid = threadIdx.x;

    if (bid < 4) {                                // ---- topk ----
        extern __shared__ unsigned long long keys[];   // 8192 max
        __shared__ int cnt;
        const int b = bid;
        const float* e = edge + b * HWN;
        if (tid == 0) cnt = 0;
        __syncthreads();
        for (int i = tid; i < HWN; i += 1024) {
            float v = e[i];
            if (v >= THRV) {
                int pos = atomicAdd(&cnt, 1);
                if (pos < 8192)
                    keys[pos] = ((unsigned long long)__float_as_uint(v) << 32) | (unsigned int)(~i);
            }
        }
        __syncthreads();
        int c = min(cnt, 8192);
        int n = (c <= 4096) ? 4096 : 8192;
        for (int i = c + tid; i < n; i += 1024) keys[i] = 0ull;
        __syncthreads();
        for (int k = 2; k <= n; k <<= 1) {
            for (int j = k >> 1; j > 0; j >>= 1) {
                for (int i = tid; i < n; i += 1024) {
                    int ixj = i ^ j;
                    if (ixj > i) {
                        unsigned long long a = keys[i], cc2 = keys[ixj];
                        bool up = (i & k) == 0;
                        if (up ? (a < cc2) : (a > cc2)) { keys[i] = cc2; keys[ixj] = a; }
                    }
                }
                __syncthreads();
            }
        }
        for (int p = tid; p < PP; p += 1024)
            g_idx[b * PP + p] = (int)(~(unsigned int)(keys[p] & 0xFFFFFFFFu));
    } else if (bid < 68) {                        // ---- W splits ----
        const int gt = (bid - 4) * 1024 + tid;    // 65536 threads
        const float4* W4 = (const float4*)wadj;
        for (int i = gt; i < PP * PP / 4; i += 64 * 1024) {
            float4 v = W4[i];
            __nv_bfloat16 h0 = __float2bfloat16_rn(v.x), h1 = __float2bfloat16_rn(v.y);
            __nv_bfloat16 h2 = __float2bfloat16_rn(v.z), h3 = __float2bfloat16_rn(v.w);
            uint2 hp, lp;
            hp.x = pack_hi2(v.x, v.y); hp.y = pack_hi2(v.z, v.w);
            lp.x = pack_hi2(v.x - __bfloat162float(h0), v.y - __bfloat162float(h1));
            lp.y = pack_hi2(v.z - __bfloat162float(h2), v.w - __bfloat162float(h3));
            *(uint2*)(g_Whi + (size_t)i * 4) = hp;
            *(uint2*)(g_Wlo + (size_t)i * 4) = lp;
        }
        const float4* G4 = (const float4*)wwg;
        if (gt < CC * CC / 4) {
            float4 v = G4[gt];
            __nv_bfloat16 h0 = __float2bfloat16_rn(v.x), h1 = __float2bfloat16_rn(v.y);
            __nv_bfloat16 h2 = __float2bfloat16_rn(v.z), h3 = __float2bfloat16_rn(v.w);
            uint2 hp, lp;
            hp.x = pack_hi2(v.x, v.y); hp.y = pack_hi2(v.z, v.w);
            lp.x = pack_hi2(v.x - __bfloat162float(h0), v.y - __bfloat162float(h1));
            lp.y = pack_hi2(v.z - __bfloat162float(h2), v.w - __bfloat162float(h3));
            *(uint2*)(g_WGhi + (size_t)gt * 4) = hp;
            *(uint2*)(g_WGlo + (size_t)gt * 4) = lp;
        }
    } else {                                      // ---- out = x ----
        const int gt = (bid - 68) * 1024 + tid;
        const float4* X4 = (const float4*)x;
        float4* O4 = (float4*)out;
        const int NT = BB * CC * HWN / 4;
        for (int i = gt; i < NT; i += 128 * 1024)
            O4[i] = X4[i];
    }
}

// ---------------- gather: x -> Gt bf16 hi/lo [c][p] + Gf fp32 [p][c]
__global__ __launch_bounds__(256) void gather_kernel(const float* __restrict__ x)
{
    __shared__ float tile[64][65];
    __shared__ int jj[64];
    const int p0 = blockIdx.x * 64, c0 = blockIdx.y * 64, b = blockIdx.z;
    const int tid = threadIdx.x;
    if (tid < 64) jj[tid] = g_idx[b * PP + p0 + tid];
    __syncthreads();

    #pragma unroll
    for (int e = tid; e < 64 * 64; e += 256) {
        int pc = e & 63, cl = e >> 6;
        tile[pc][cl] = x[((size_t)b * CC + c0 + cl) * HWN + jj[pc]];
    }
    __syncthreads();

    #pragma unroll
    for (int e = tid; e < 64 * 64; e += 256) {
        int cl = e >> 6, pc = e & 63;
        float v = tile[pc][cl];
        __nv_bfloat16 h = __float2bfloat16_rn(v);
        size_t o = ((size_t)b * CC + c0 + cl) * PP + p0 + pc;
        g_Gthi[o] = h;
        g_Gtlo[o] = __float2bfloat16_rn(v - __bfloat162float(h));
    }
    #pragma unroll
    for (int e = tid; e < 64 * 64; e += 256) {
        int pc = e >> 6, cl = e & 63;
        g_Gf[((size_t)b * PP + p0 + pc) * CC + c0 + cl] = tile[pc][cl];
    }
}

// ---------------- mma.sync GEMM geometry ---------------------------
// CTA 128(M) x 64(N), BK=32, 256 thr, warps 4(m) x 2(n), warp 32x32.
// Per kk-step: 4 A-LDSM + 4 B-LDSM feed 24 MMAs (ratio 3.0).
// smem stage: Ah/Al [128][40], Bh/Bl [64][40] bf16; 80B padded rows.
#define STAGE 30720
#define ROWE  40

// Fragment load + MMA block shared by both GEMMs (warp 32x32)
#define FRAG_MMA(stb) \
    _Pragma("unroll") \
    for (int kk = 0; kk < 2; kk++) { \
        const int kb0 = kk * 16; \
        uint32_t ah[2][4], al[2][4], bh[2][4], bl[2][4]; \
        _Pragma("unroll") \
        for (int mt = 0; mt < 2; mt++) { \
            uint32_t aaddr = (stb) + ((wm * 32 + mt * 16 + (lane & 15)) * ROWE \
                                      + kb0 + ((lane >> 4) << 3)) * 2; \
            LDSM4(ah[mt][0], ah[mt][1], ah[mt][2], ah[mt][3], aaddr); \
            LDSM4(al[mt][0], al[mt][1], al[mt][2], al[mt][3], aaddr + 10240); \
        } \
        _Pragma("unroll") \
        for (int u = 0; u < 2; u++) { \
            uint32_t baddr = (stb) + 20480 \
                + ((wn * 32 + u * 16 + ((lane >> 4) << 3) + (lane & 7)) * ROWE \
                   + kb0 + (((lane >> 3) & 1) << 3)) * 2; \
            LDSM4(bh[u][0], bh[u][1], bh[u][2], bh[u][3], baddr); \
            LDSM4(bl[u][0], bl[u][1], bl[u][2], bl[u][3], baddr + 5120); \
        } \
        _Pragma("unroll") \
        for (int mt = 0; mt < 2; mt++) \
            _Pragma("unroll") \
            for (int nt = 0; nt < 4; nt++) { \
                const int u = nt >> 1, v = (nt & 1) * 2; \
                MMA_BF16(acc[mt][nt], ah[mt][0], ah[mt][1], ah[mt][2], ah[mt][3], \
                         bh[u][v], bh[u][v + 1]); \
                MMA_BF16(acc[mt][nt], al[mt][0], al[mt][1], al[mt][2], al[mt][3], \
                         bh[u][v], bh[u][v + 1]); \
                MMA_BF16(acc[mt][nt], ah[mt][0], ah[mt][1], ah[mt][2], ah[mt][3], \
                         bl[u][v], bl[u][v + 1]); \
            } \
    }

// ---------------- GEMM1: Z = relu(BN(W @ G)) + G --------------------
__global__ __launch_bounds__(256, 2) void gemm1_mma(
    const float* __restrict__ ga, const float* __restrict__ be)
{
    extern __shared__ __align__(16) char sm[];
    const uint32_t sb = smem_u32(sm);
    const int tid = threadIdx.x;
    const int b = blockIdx.z, m0 = blockIdx.y * 128, n0 = blockIdx.x * 64;
    const int lane = tid & 31, warp = tid >> 5;
    const int grp = lane >> 2, qid = lane & 3;
    const int wm = warp >> 1, wn = warp & 1;   // 4 m-warps x 2 n-warps

    float acc[2][4][4];
    #pragma unroll
    for (int i = 0; i < 2; i++)
        #pragma unroll
        for (int j = 0; j < 4; j++)
            #pragma unroll
            for (int r = 0; r < 4; r++) acc[i][j][r] = 0.0f;

#define G1_FILL(st, k0) do { \
    uint32_t base_ = sb + (st) * STAGE; \
    for (int i_ = tid; i_ < 512; i_ += 256) { \
        int r_ = i_ >> 2, c8_ = (i_ & 3) * 8; \
        uint32_t d_ = base_ + r_ * 80 + c8_ * 2; \
        CPA16(d_,         g_Whi + (size_t)(m0 + r_) * PP + (k0) + c8_); \
        CPA16(d_ + 10240, g_Wlo + (size_t)(m0 + r_) * PP + (k0) + c8_); \
    } \
    { \
        int i_ = tid; \
        int r_ = i_ >> 2, c8_ = (i_ & 3) * 8; \
        uint32_t d_ = base_ + 20480 + r_ * 80 + c8_ * 2; \
        CPA16(d_,        g_Gthi + ((size_t)b * CC + n0 + r_) * PP + (k0) + c8_); \
        CPA16(d_ + 5120, g_Gtlo + ((size_t)b * CC + n0 + r_) * PP + (k0) + c8_); \
    } } while (0)

    G1_FILL(0, 0);
    CPA_COMMIT();

    const int NIT = PP / 32;   // 64
    #pragma unroll 1
    for (int it = 0; it < NIT; it++) {
        if (it + 1 < NIT) G1_FILL((it + 1) & 1, (it + 1) * 32);
        CPA_COMMIT();
        CPA_WAIT1();
        __syncthreads();
        const uint32_t stb = sb + (it & 1) * STAGE;
        FRAG_MMA(stb)
        __syncthreads();
    }

    const float inv = rsqrtf(1.0f + 1e-5f);
    #pragma unroll
    for (int mt = 0; mt < 2; mt++) {
        int row0 = m0 + wm * 32 + mt * 16 + grp;
        int row1 = row0 + 8;
        float s0 = inv * ga[row0], t0 = be[row0];
        float s1 = inv * ga[row1], t1 = be[row1];
        #pragma unroll
        for (int nt = 0; nt < 4; nt++) {
            int col = n0 + wn * 32 + nt * 8 + qid * 2;
            size_t o0 = ((size_t)b * PP + row0) * CC + col;
            size_t o1 = ((size_t)b * PP + row1) * CC + col;
            float2 gf0 = *(const float2*)(g_Gf + o0);
            float2 gf1 = *(const float2*)(g_Gf + o1);
            float v00 = fmaxf(fmaf(acc[mt][nt][0], s0, t0), 0.0f) + gf0.x;
            float v01 = fmaxf(fmaf(acc[mt][nt][1], s0, t0), 0.0f) + gf0.y;
            float v10 = fmaxf(fmaf(acc[mt][nt][2], s1, t1), 0.0f) + gf1.x;
            float v11 = fmaxf(fmaf(acc[mt][nt][3], s1, t1), 0.0f) + gf1.y;
            __nv_bfloat162 h0 = __floats2bfloat162_rn(v00, v01);
            __nv_bfloat162 h1 = __floats2bfloat162_rn(v10, v11);
            *(uint32_t*)(g_Zhi + o0) = *(uint32_t*)&h0;
            *(uint32_t*)(g_Zhi + o1) = *(uint32_t*)&h1;
            __nv_bfloat162 l0 = __floats2bfloat162_rn(v00 - __bfloat162float(h0.x),
                                                      v01 - __bfloat162float(h0.y));
            __nv_bfloat162 l1 = __floats2bfloat162_rn(v10 - __bfloat162float(h1.x),
                                                      v11 - __bfloat162float(h1.y));
            *(uint32_t*)(g_Zlo + o0) = *(uint32_t*)&l0;
            *(uint32_t*)(g_Zlo + o1) = *(uint32_t*)&l1;
        }
    }
#undef G1_FILL
}

// ---------------- GEMM2: R[b][d][p] = relu(BN(WG @ Z^T)), DENSE -----
__global__ __launch_bounds__(256, 2) void gemm2_mma(
    const float* __restrict__ gw, const float* __restrict__ bw)
{
    extern __shared__ __align__(16) char sm[];
    const uint32_t sb = smem_u32(sm);
    const int tid = threadIdx.x;
    const int b = blockIdx.z, m0 = blockIdx.y * 128, n0 = blockIdx.x * 64;
    const int lane = tid & 31, warp = tid >> 5;
    const int grp = lane >> 2, qid = lane & 3;
    const int wm = warp >> 1, wn = warp & 1;

    float acc[2][4][4];
    #pragma unroll
    for (int i = 0; i < 2; i++)
        #pragma unroll
        for (int j = 0; j < 4; j++)
            #pragma unroll
            for (int r = 0; r < 4; r++) acc[i][j][r] = 0.0f;

#define G2_FILL(st, k0) do { \
    uint32_t base_ = sb + (st) * STAGE; \
    for (int i_ = tid; i_ < 512; i_ += 256) { \
        int r_ = i_ >> 2, c8_ = (i_ & 3) * 8; \
        uint32_t d_ = base_ + r_ * 80 + c8_ * 2; \
        CPA16(d_,         g_WGhi + (size_t)(m0 + r_) * CC + (k0) + c8_); \
        CPA16(d_ + 10240, g_WGlo + (size_t)(m0 + r_) * CC + (k0) + c8_); \
    } \
    { \
        int i_ = tid; \
        int r_ = i_ >> 2, c8_ = (i_ & 3) * 8; \
        uint32_t d_ = base_ + 20480 + r_ * 80 + c8_ * 2; \
        CPA16(d_,        g_Zhi + ((size_t)b * PP + n0 + r_) * CC + (k0) + c8_); \
        CPA16(d_ + 5120, g_Zlo + ((size_t)b * PP + n0 + r_) * CC + (k0) + c8_); \
    } } while (0)

    G2_FILL(0, 0);
    CPA_COMMIT();

    const int NIT = CC / 32;   // 8
    #pragma unroll 1
    for (int it = 0; it < NIT; it++) {
        if (it + 1 < NIT) G2_FILL((it + 1) & 1, (it + 1) * 32);
        CPA_COMMIT();
        CPA_WAIT1();
        __syncthreads();
        const uint32_t stb = sb + (it & 1) * STAGE;
        FRAG_MMA(stb)
        __syncthreads();
    }

    // dense epilogue: BN(axis=d) + ReLU -> R[b][d][p], coalesced float2
    const float inv = rsqrtf(1.0f + 1e-5f);
    #pragma unroll
    for (int mt = 0; mt < 2; mt++) {
        int row0 = m0 + wm * 32 + mt * 16 + grp;   // d
        int row1 = row0 + 8;
        float s0 = inv * gw[row0], t0 = bw[row0];
        float s1 = inv * gw[row1], t1 = bw[row1];
        #pragma unroll
        for (int nt = 0; nt < 4; nt++) {
            int col = n0 + wn * 32 + nt * 8 + qid * 2;   // p
            float2 v0, v1;
            v0.x = fmaxf(fmaf(acc[mt][nt][0], s0, t0), 0.0f);
            v0.y = fmaxf(fmaf(acc[mt][nt][1], s0, t0), 0.0f);
            v1.x = fmaxf(fmaf(acc[mt][nt][2], s1, t1), 0.0f);
            v1.y = fmaxf(fmaf(acc[mt][nt][3], s1, t1), 0.0f);
            *(float2*)(g_R + ((size_t)b * CC + row0) * PP + col) = v0;
            *(float2*)(g_R + ((size_t)b * CC + row1) * PP + col) = v1;
        }
    }
#undef G2_FILL
}

// ---------------- scatter: out[b][d][idx[p]] = R[b][d][p] -----------
__global__ __launch_bounds__(256) void scatter_kernel(float* __restrict__ out)
{
    __shared__ int jj[256];
    const int p0 = blockIdx.x * 256, d0 = blockIdx.y * 8, b = blockIdx.z;
    const int tid = threadIdx.x;
    jj[tid] = g_idx[b * PP + p0 + tid];
    __syncthreads();

    const int j = jj[tid];
    const float* Rb = g_R + ((size_t)b * CC + d0) * PP + p0 + tid;
    float* ob = out + ((size_t)b * CC + d0) * HWN + j;
    #pragma unroll
    for (int k = 0; k < 8; k++)
        ob[(size_t)k * HWN] = Rb[(size_t)k * PP];
}

// ---------------------------------------------------------------
extern "C" void kernel_launch(void* const* d_in, const int* in_sizes, int n_in,
                              void* d_out, int out_size)
{
    const float* x    = (const float*)d_in[0];
    const float* edge = (const float*)d_in[1];
    const float* wadj = (const float*)d_in[2];
    const float* ga   = (const float*)d_in[3];
    const float* be   = (const float*)d_in[4];
    const float* wwg  = (const float*)d_in[5];
    const float* gw   = (const float*)d_in[6];
    const float* bw   = (const float*)d_in[7];
    float* out = (float*)d_out;

    cudaFuncSetAttribute(prep_kernel, cudaFuncAttributeMaxDynamicSharedMemorySize, 65536);
    cudaFuncSetAttribute(gemm1_mma,   cudaFuncAttributeMaxDynamicSharedMemorySize, 2 * STAGE);
    cudaFuncSetAttribute(gemm2_mma,   cudaFuncAttributeMaxDynamicSharedMemorySize, 2 * STAGE);

    // fused: topk (0-3) + W splits (4-67) + out=x copy (68-195)
    prep_kernel<<<196, 1024, 65536>>>(edge, x, wadj, wwg, out);

    // gather (needs idx)
    {
        dim3 g(PP / 64, CC / 64, BB);   // (32, 4, 4)
        gather_kernel<<<g, 256>>>(x);
    }

    // GEMM1 + BN + ReLU + residual
    {
        dim3 g(CC / 64, PP / 128, BB);  // (4, 16, 4)
        gemm1_mma<<<g, 256, 2 * STAGE>>>(ga, be);
    }
    // GEMM2 + BN + ReLU -> dense R
    {
        dim3 g(PP / 64, CC / 128, BB);  // (32, 2, 4)
        gemm2_mma<<<g, 256, 2 * STAGE>>>(gw, bw);
    }
    // scatter R into out (out already = x from prep)
    {
        dim3 g(PP / 256, CC / 8, BB);   // (8, 32, 4)
        scatter_kernel<<<g, 256>>>(out);
    }
}

// round 14
// speedup vs baseline: 1.5910x; 1.0744x over previous
#include <cuda_runtime.h>
#include <cuda_fp16.h>
#include <cstdint>

#define BB 4
#define CC 256
#define HWN 16384
#define PP 2048
#define THRV 0.8f

// ---------------- scratch (no allocations allowed) ----------------
__device__ __half g_Whi[PP * PP];          // Wadj fp16 hi [o][p]
__device__ __half g_Wlo[PP * PP];          // Wadj fp16 lo
__device__ __half g_Gt[BB * CC * PP];      // G^T fp16 [b][c][p]  (B side, hi only)
__device__ float  g_Gf[BB * PP * CC];      // G fp32 [b][p][c] (residual)
__device__ __half g_Z[BB * PP * CC];       // stage-1 out fp16 [b][p][c]
__device__ __half g_WGhi[CC * CC];         // Wwg fp16 hi [d][c]
__device__ __half g_WGlo[CC * CC];
__device__ float  g_R[BB * CC * PP];       // dense stage-2 out [b][d][p]
__device__ int    g_idx[BB * PP];          // topk indices

// ---------------- PTX helpers (baseline ISA: sm_80+) ---------------
__device__ __forceinline__ uint32_t smem_u32(const void* p) {
    uint32_t a;
    asm("{ .reg .u64 t; cvta.to.shared.u64 t, %1; cvt.u32.u64 %0, t; }" : "=r"(a) : "l"(p));
    return a;
}
#define CPA16(dst_u32, src_ptr) \
    asm volatile("cp.async.cg.shared.global [%0], [%1], 16;" :: "r"(dst_u32), "l"(src_ptr) : "memory")
#define CPA_COMMIT() asm volatile("cp.async.commit_group;" ::: "memory")
#define CPA_WAIT1()  asm volatile("cp.async.wait_group 1;" ::: "memory")

#define MMA_FP16(c, a0, a1, a2, a3, b0, b1) \
    asm volatile("mma.sync.aligned.m16n8k16.row.col.f32.f16.f16.f32 " \
        "{%0,%1,%2,%3}, {%4,%5,%6,%7}, {%8,%9}, {%0,%1,%2,%3};" \
        : "+f"((c)[0]), "+f"((c)[1]), "+f"((c)[2]), "+f"((c)[3]) \
        : "r"(a0), "r"(a1), "r"(a2), "r"(a3), "r"(b0), "r"(b1))

#define LDSM4(r0, r1, r2, r3, addr) \
    asm volatile("ldmatrix.sync.aligned.m8n8.x4.shared.b16 {%0,%1,%2,%3}, [%4];" \
        : "=r"(r0), "=r"(r1), "=r"(r2), "=r"(r3) : "r"(addr))

__device__ __forceinline__ uint32_t pack_h2(float a, float b) {
    __half2 t = __floats2half2_rn(a, b);
    return *(uint32_t*)&t;
}

// ---------------- fused prep: topk + W splits + out=x copy ----------
__global__ __launch_bounds__(1024) void prep_kernel(
    const float* __restrict__ edge, const float* __restrict__ x,
    const float* __restrict__ wadj, const float* __restrict__ wwg,
    float* __restrict__ out)
{
    const int bid = blockIdx.x, tid = threadIdx.x;

    if (bid < 4) {                                // ---- topk ----
        extern __shared__ unsigned long long keys[];   // 8192 max
        __shared__ int cnt;
        const int b = bid;
        const float* e = edge + b * HWN;
        if (tid == 0) cnt = 0;
        __syncthreads();
        for (int i = tid; i < HWN; i += 1024) {
            float v = e[i];
            if (v >= THRV) {
                int pos = atomicAdd(&cnt, 1);
                if (pos < 8192)
                    keys[pos] = ((unsigned long long)__float_as_uint(v) << 32) | (unsigned int)(~i);
            }
        }
        __syncthreads();
        int c = min(cnt, 8192);
        int n = (c <= 4096) ? 4096 : 8192;
        for (int i = c + tid; i < n; i += 1024) keys[i] = 0ull;
        __syncthreads();
        for (int k = 2; k <= n; k <<= 1) {
            for (int j = k >> 1; j > 0; j >>= 1) {
                for (int i = tid; i < n; i += 1024) {
                    int ixj = i ^ j;
                    if (ixj > i) {
                        unsigned long long a = keys[i], cc2 = keys[ixj];
                        bool up = (i & k) == 0;
                        if (up ? (a < cc2) : (a > cc2)) { keys[i] = cc2; keys[ixj] = a; }
                    }
                }
                __syncthreads();
            }
        }
        for (int p = tid; p < PP; p += 1024)
            g_idx[b * PP + p] = (int)(~(unsigned int)(keys[p] & 0xFFFFFFFFu));
    } else if (bid < 68) {                        // ---- W splits ----
        const int gt = (bid - 4) * 1024 + tid;    // 65536 threads
        const float4* W4 = (const float4*)wadj;
        for (int i = gt; i < PP * PP / 4; i += 64 * 1024) {
            float4 v = W4[i];
            __half h0 = __float2half_rn(v.x), h1 = __float2half_rn(v.y);
            __half h2 = __float2half_rn(v.z), h3 = __float2half_rn(v.w);
            uint2 hp, lp;
            hp.x = pack_h2(v.x, v.y); hp.y = pack_h2(v.z, v.w);
            lp.x = pack_h2(v.x - __half2float(h0), v.y - __half2float(h1));
            lp.y = pack_h2(v.z - __half2float(h2), v.w - __half2float(h3));
            *(uint2*)(g_Whi + (size_t)i * 4) = hp;
            *(uint2*)(g_Wlo + (size_t)i * 4) = lp;
        }
        const float4* G4 = (const float4*)wwg;
        if (gt < CC * CC / 4) {
            float4 v = G4[gt];
            __half h0 = __float2half_rn(v.x), h1 = __float2half_rn(v.y);
            __half h2 = __float2half_rn(v.z), h3 = __float2half_rn(v.w);
            uint2 hp, lp;
            hp.x = pack_h2(v.x, v.y); hp.y = pack_h2(v.z, v.w);
            lp.x = pack_h2(v.x - __half2float(h0), v.y - __half2float(h1));
            lp.y = pack_h2(v.z - __half2float(h2), v.w - __half2float(h3));
            *(uint2*)(g_WGhi + (size_t)gt * 4) = hp;
            *(uint2*)(g_WGlo + (size_t)gt * 4) = lp;
        }
    } else {                                      // ---- out = x ----
        const int gt = (bid - 68) * 1024 + tid;
        const float4* X4 = (const float4*)x;
        float4* O4 = (float4*)out;
        const int NT = BB * CC * HWN / 4;
        for (int i = gt; i < NT; i += 128 * 1024)
            O4[i] = X4[i];
    }
}

// ---------------- gather: x -> Gt fp16 [c][p] + Gf fp32 [p][c] ------
__global__ __launch_bounds__(256) void gather_kernel(const float* __restrict__ x)
{
    __shared__ float tile[64][65];
    __shared__ int jj[64];
    const int p0 = blockIdx.x * 64, c0 = blockIdx.y * 64, b = blockIdx.z;
    const int tid = threadIdx.x;
    if (tid < 64) jj[tid] = g_idx[b * PP + p0 + tid];
    __syncthreads();

    #pragma unroll
    for (int e = tid; e < 64 * 64; e += 256) {
        int pc = e & 63, cl = e >> 6;
        tile[pc][cl] = x[((size_t)b * CC + c0 + cl) * HWN + jj[pc]];
    }
    __syncthreads();

    #pragma unroll
    for (int e = tid; e < 64 * 64; e += 256) {
        int cl = e >> 6, pc = e & 63;
        g_Gt[((size_t)b * CC + c0 + cl) * PP + p0 + pc] =
            __float2half_rn(tile[pc][cl]);
    }
    #pragma unroll
    for (int e = tid; e < 64 * 64; e += 256) {
        int pc = e >> 6, cl = e & 63;
        g_Gf[((size_t)b * PP + p0 + pc) * CC + c0 + cl] = tile[pc][cl];
    }
}

// ---------------- mma.sync GEMM geometry ---------------------------
// CTA 128(M) x 64(N), BK=32, 256 thr, warps 4(m) x 2(n), warp 32x32.
// fp16 2-product: C = (Ah+Al)*Bh. Stage: Ah[128][40], Al[128][40],
// Bh[64][40]; 80B padded rows. STAGE = 25600 B, 2 stages.
#define STAGE 25600
#define ROWE  40

// Fragment load + MMA block shared by both GEMMs (warp 32x32)
#define FRAG_MMA(stb) \
    _Pragma("unroll") \
    for (int kk = 0; kk < 2; kk++) { \
        const int kb0 = kk * 16; \
        uint32_t ah[2][4], al[2][4], bh[2][4]; \
        _Pragma("unroll") \
        for (int mt = 0; mt < 2; mt++) { \
            uint32_t aaddr = (stb) + ((wm * 32 + mt * 16 + (lane & 15)) * ROWE \
                                      + kb0 + ((lane >> 4) << 3)) * 2; \
            LDSM4(ah[mt][0], ah[mt][1], ah[mt][2], ah[mt][3], aaddr); \
            LDSM4(al[mt][0], al[mt][1], al[mt][2], al[mt][3], aaddr + 10240); \
        } \
        _Pragma("unroll") \
        for (int u = 0; u < 2; u++) { \
            uint32_t baddr = (stb) + 20480 \
                + ((wn * 32 + u * 16 + ((lane >> 4) << 3) + (lane & 7)) * ROWE \
                   + kb0 + (((lane >> 3) & 1) << 3)) * 2; \
            LDSM4(bh[u][0], bh[u][1], bh[u][2], bh[u][3], baddr); \
        } \
        _Pragma("unroll") \
        for (int mt = 0; mt < 2; mt++) \
            _Pragma("unroll") \
            for (int nt = 0; nt < 4; nt++) { \
                const int u = nt >> 1, v = (nt & 1) * 2; \
                MMA_FP16(acc[mt][nt], ah[mt][0], ah[mt][1], ah[mt][2], ah[mt][3], \
                         bh[u][v], bh[u][v + 1]); \
                MMA_FP16(acc[mt][nt], al[mt][0], al[mt][1], al[mt][2], al[mt][3], \
                         bh[u][v], bh[u][v + 1]); \
            } \
    }

// ---------------- GEMM1: Z = relu(BN(W @ G)) + G --------------------
__global__ __launch_bounds__(256, 2) void gemm1_mma(
    const float* __restrict__ ga, const float* __restrict__ be)
{
    extern __shared__ __align__(16) char sm[];
    const uint32_t sb = smem_u32(sm);
    const int tid = threadIdx.x;
    const int b = blockIdx.z, m0 = blockIdx.y * 128, n0 = blockIdx.x * 64;
    const int lane = tid & 31, warp = tid >> 5;
    const int grp = lane >> 2, qid = lane & 3;
    const int wm = warp >> 1, wn = warp & 1;   // 4 m-warps x 2 n-warps

    float acc[2][4][4];
    #pragma unroll
    for (int i = 0; i < 2; i++)
        #pragma unroll
        for (int j = 0; j < 4; j++)
            #pragma unroll
            for (int r = 0; r < 4; r++) acc[i][j][r] = 0.0f;

#define G1_FILL(st, k0) do { \
    uint32_t base_ = sb + (st) * STAGE; \
    for (int i_ = tid; i_ < 512; i_ += 256) { \
        int r_ = i_ >> 2, c8_ = (i_ & 3) * 8; \
        uint32_t d_ = base_ + r_ * 80 + c8_ * 2; \
        CPA16(d_,         g_Whi + (size_t)(m0 + r_) * PP + (k0) + c8_); \
        CPA16(d_ + 10240, g_Wlo + (size_t)(m0 + r_) * PP + (k0) + c8_); \
    } \
    { \
        int i_ = tid; \
        int r_ = i_ >> 2, c8_ = (i_ & 3) * 8; \
        uint32_t d_ = base_ + 20480 + r_ * 80 + c8_ * 2; \
        CPA16(d_, g_Gt + ((size_t)b * CC + n0 + r_) * PP + (k0) + c8_); \
    } } while (0)

    G1_FILL(0, 0);
    CPA_COMMIT();

    const int NIT = PP / 32;   // 64
    #pragma unroll 1
    for (int it = 0; it < NIT; it++) {
        if (it + 1 < NIT) G1_FILL((it + 1) & 1, (it + 1) * 32);
        CPA_COMMIT();
        CPA_WAIT1();
        __syncthreads();
        const uint32_t stb = sb + (it & 1) * STAGE;
        FRAG_MMA(stb)
        __syncthreads();
    }

    const float inv = rsqrtf(1.0f + 1e-5f);
    #pragma unroll
    for (int mt = 0; mt < 2; mt++) {
        int row0 = m0 + wm * 32 + mt * 16 + grp;
        int row1 = row0 + 8;
        float s0 = inv * ga[row0], t0 = be[row0];
        float s1 = inv * ga[row1], t1 = be[row1];
        #pragma unroll
        for (int nt = 0; nt < 4; nt++) {
            int col = n0 + wn * 32 + nt * 8 + qid * 2;
            size_t o0 = ((size_t)b * PP + row0) * CC + col;
            size_t o1 = ((size_t)b * PP + row1) * CC + col;
            float2 gf0 = *(const float2*)(g_Gf + o0);
            float2 gf1 = *(const float2*)(g_Gf + o1);
            float v00 = fmaxf(fmaf(acc[mt][nt][0], s0, t0), 0.0f) + gf0.x;
            float v01 = fmaxf(fmaf(acc[mt][nt][1], s0, t0), 0.0f) + gf0.y;
            float v10 = fmaxf(fmaf(acc[mt][nt][2], s1, t1), 0.0f) + gf1.x;
            float v11 = fmaxf(fmaf(acc[mt][nt][3], s1, t1), 0.0f) + gf1.y;
            *(uint32_t*)(g_Z + o0) = pack_h2(v00, v01);
            *(uint32_t*)(g_Z + o1) = pack_h2(v10, v11);
        }
    }
#undef G1_FILL
}

// ---------------- GEMM2: R[b][d][p] = relu(BN(WG @ Z^T)), DENSE -----
__global__ __launch_bounds__(256, 2) void gemm2_mma(
    const float* __restrict__ gw, const float* __restrict__ bw)
{
    extern __shared__ __align__(16) char sm[];
    const uint32_t sb = smem_u32(sm);
    const int tid = threadIdx.x;
    const int b = blockIdx.z, m0 = blockIdx.y * 128, n0 = blockIdx.x * 64;
    const int lane = tid & 31, warp = tid >> 5;
    const int grp = lane >> 2, qid = lane & 3;
    const int wm = warp >> 1, wn = warp & 1;

    float acc[2][4][4];
    #pragma unroll
    for (int i = 0; i < 2; i++)
        #pragma unroll
        for (int j = 0; j < 4; j++)
            #pragma unroll
            for (int r = 0; r < 4; r++) acc[i][j][r] = 0.0f;

#define G2_FILL(st, k0) do { \
    uint32_t base_ = sb + (st) * STAGE; \
    for (int i_ = tid; i_ < 512; i_ += 256) { \
        int r_ = i_ >> 2, c8_ = (i_ & 3) * 8; \
        uint32_t d_ = base_ + r_ * 80 + c8_ * 2; \
        CPA16(d_,         g_WGhi + (size_t)(m0 + r_) * CC + (k0) + c8_); \
        CPA16(d_ + 10240, g_WGlo + (size_t)(m0 + r_) * CC + (k0) + c8_); \
    } \
    { \
        int i_ = tid; \
        int r_ = i_ >> 2, c8_ = (i_ & 3) * 8; \
        uint32_t d_ = base_ + 20480 + r_ * 80 + c8_ * 2; \
        CPA16(d_, g_Z + ((size_t)b * PP + n0 + r_) * CC + (k0) + c8_); \
    } } while (0)

    G2_FILL(0, 0);
    CPA_COMMIT();

    const int NIT = CC / 32;   // 8
    #pragma unroll 1
    for (int it = 0; it < NIT; it++) {
        if (it + 1 < NIT) G2_FILL((it + 1) & 1, (it + 1) * 32);
        CPA_COMMIT();
        CPA_WAIT1();
        __syncthreads();
        const uint32_t stb = sb + (it & 1) * STAGE;
        FRAG_MMA(stb)
        __syncthreads();
    }

    // dense epilogue: BN(axis=d) + ReLU -> R[b][d][p], coalesced float2
    const float inv = rsqrtf(1.0f + 1e-5f);
    #pragma unroll
    for (int mt = 0; mt < 2; mt++) {
        int row0 = m0 + wm * 32 + mt * 16 + grp;   // d
        int row1 = row0 + 8;
        float s0 = inv * gw[row0], t0 = bw[row0];
        float s1 = inv * gw[row1], t1 = bw[row1];
        #pragma unroll
        for (int nt = 0; nt < 4; nt++) {
            int col = n0 + wn * 32 + nt * 8 + qid * 2;   // p
            float2 v0, v1;
            v0.x = fmaxf(fmaf(acc[mt][nt][0], s0, t0), 0.0f);
            v0.y = fmaxf(fmaf(acc[mt][nt][1], s0, t0), 0.0f);
            v1.x = fmaxf(fmaf(acc[mt][nt][2], s1, t1), 0.0f);
            v1.y = fmaxf(fmaf(acc[mt][nt][3], s1, t1), 0.0f);
            *(float2*)(g_R + ((size_t)b * CC + row0) * PP + col) = v0;
            *(float2*)(g_R + ((size_t)b * CC + row1) * PP + col) = v1;
        }
    }
#undef G2_FILL
}

// ---------------- scatter: out[b][d][idx[p]] = R[b][d][p] -----------
__global__ __launch_bounds__(256) void scatter_kernel(float* __restrict__ out)
{
    __shared__ int jj[256];
    const int p0 = blockIdx.x * 256, d0 = blockIdx.y * 8, b = blockIdx.z;
    const int tid = threadIdx.x;
    jj[tid] = g_idx[b * PP + p0 + tid];
    __syncthreads();

    const int j = jj[tid];
    const float* Rb = g_R + ((size_t)b * CC + d0) * PP + p0 + tid;
    float* ob = out + ((size_t)b * CC + d0) * HWN + j;
    #pragma unroll
    for (int k = 0; k < 8; k++)
        ob[(size_t)k * HWN] = Rb[(size_t)k * PP];
}

// ---------------------------------------------------------------
extern "C" void kernel_launch(void* const* d_in, const int* in_sizes, int n_in,
                              void* d_out, int out_size)
{
    const float* x    = (const float*)d_in[0];
    const float* edge = (const float*)d_in[1];
    const float* wadj = (const float*)d_in[2];
    const float* ga   = (const float*)d_in[3];
    const float* be   = (const float*)d_in[4];
    const float* wwg  = (const float*)d_in[5];
    const float* gw   = (const float*)d_in[6];
    const float* bw   = (const float*)d_in[7];
    float* out = (float*)d_out;

    cudaFuncSetAttribute(prep_kernel, cudaFuncAttributeMaxDynamicSharedMemorySize, 65536);
    cudaFuncSetAttribute(gemm1_mma,   cudaFuncAttributeMaxDynamicSharedMemorySize, 2 * STAGE);
    cudaFuncSetAttribute(gemm2_mma,   cudaFuncAttributeMaxDynamicSharedMemorySize, 2 * STAGE);

    // fused: topk (0-3) + W splits (4-67) + out=x copy (68-195)
    prep_kernel<<<196, 1024, 65536>>>(edge, x, wadj, wwg, out);

    // gather (needs idx)
    {
        dim3 g(PP / 64, CC / 64, BB);   // (32, 4, 4)
        gather_kernel<<<g, 256>>>(x);
    }

    // GEMM1 + BN + ReLU + residual
    {
        dim3 g(CC / 64, PP / 128, BB);  // (4, 16, 4)
        gemm1_mma<<<g, 256, 2 * STAGE>>>(ga, be);
    }
    // GEMM2 + BN + ReLU -> dense R
    {
        dim3 g(PP / 64, CC / 128, BB);  // (32, 2, 4)
        gemm2_mma<<<g, 256, 2 * STAGE>>>(gw, bw);
    }
    // scatter R into out (out already = x from prep)
    {
        dim3 g(PP / 256, CC / 8, BB);   // (8, 32, 4)
        scatter_kernel<<<g, 256>>>(out);
    }
}

// round 16
// speedup vs baseline: 1.8838x; 1.1840x over previous
#include <cuda_runtime.h>
#include <cuda_fp16.h>
#include <cstdint>

#define BB 4
#define CC 256
#define HWN 16384
#define PP 2048
#define THRV 0.8f

// ---------------- scratch (no allocations allowed) ----------------
__device__ __half g_W[PP * PP];            // Wadj fp16 [o][p]
__device__ __half g_Gt[BB * CC * PP];      // G^T fp16 [b][c][p]  (B side)
__device__ float  g_Gf[BB * PP * CC];      // G fp32 [b][p][c] (residual)
__device__ __half g_Z[BB * PP * CC];       // stage-1 out fp16 [b][p][c]
__device__ __half g_WG[CC * CC];           // Wwg fp16 [d][c]
__device__ float  g_R[BB * CC * PP];       // dense stage-2 out [b][d][p]
__device__ int    g_idx[BB * PP];          // topk indices

// ---------------- PTX helpers (baseline ISA: sm_80+) ---------------
__device__ __forceinline__ uint32_t smem_u32(const void* p) {
    uint32_t a;
    asm("{ .reg .u64 t; cvta.to.shared.u64 t, %1; cvt.u32.u64 %0, t; }" : "=r"(a) : "l"(p));
    return a;
}
#define CPA16(dst_u32, src_ptr) \
    asm volatile("cp.async.cg.shared.global [%0], [%1], 16;" :: "r"(dst_u32), "l"(src_ptr) : "memory")
#define CPA_COMMIT() asm volatile("cp.async.commit_group;" ::: "memory")
#define CPA_WAIT1()  asm volatile("cp.async.wait_group 1;" ::: "memory")

#define MMA_FP16(c, a0, a1, a2, a3, b0, b1) \
    asm volatile("mma.sync.aligned.m16n8k16.row.col.f32.f16.f16.f32 " \
        "{%0,%1,%2,%3}, {%4,%5,%6,%7}, {%8,%9}, {%0,%1,%2,%3};" \
        : "+f"((c)[0]), "+f"((c)[1]), "+f"((c)[2]), "+f"((c)[3]) \
        : "r"(a0), "r"(a1), "r"(a2), "r"(a3), "r"(b0), "r"(b1))

#define LDSM4(r0, r1, r2, r3, addr) \
    asm volatile("ldmatrix.sync.aligned.m8n8.x4.shared.b16 {%0,%1,%2,%3}, [%4];" \
        : "=r"(r0), "=r"(r1), "=r"(r2), "=r"(r3) : "r"(addr))

__device__ __forceinline__ uint32_t pack_h2(float a, float b) {
    __half2 t = __floats2half2_rn(a, b);
    return *(uint32_t*)&t;
}

// ---------------- fused prep: topk + W converts + out=x copy --------
__global__ __launch_bounds__(1024) void prep_kernel(
    const float* __restrict__ edge, const float* __restrict__ x,
    const float* __restrict__ wadj, const float* __restrict__ wwg,
    float* __restrict__ out)
{
    const int bid = blockIdx.x, tid = threadIdx.x;

    if (bid < 4) {                                // ---- topk ----
        extern __shared__ unsigned long long keys[];   // 8192 max
        __shared__ int cnt;
        const int b = bid;
        const float* e = edge + b * HWN;
        if (tid == 0) cnt = 0;
        __syncthreads();
        for (int i = tid; i < HWN; i += 1024) {
            float v = e[i];
            if (v >= THRV) {
                int pos = atomicAdd(&cnt, 1);
                if (pos < 8192)
                    keys[pos] = ((unsigned long long)__float_as_uint(v) << 32) | (unsigned int)(~i);
            }
        }
        __syncthreads();
        int c = min(cnt, 8192);
        int n = (c <= 4096) ? 4096 : 8192;
        for (int i = c + tid; i < n; i += 1024) keys[i] = 0ull;
        __syncthreads();
        for (int k = 2; k <= n; k <<= 1) {
            for (int j = k >> 1; j > 0; j >>= 1) {
                for (int i = tid; i < n; i += 1024) {
                    int ixj = i ^ j;
                    if (ixj > i) {
                        unsigned long long a = keys[i], cc2 = keys[ixj];
                        bool up = (i & k) == 0;
                        if (up ? (a < cc2) : (a > cc2)) { keys[i] = cc2; keys[ixj] = a; }
                    }
                }
                __syncthreads();
            }
        }
        for (int p = tid; p < PP; p += 1024)
            g_idx[b * PP + p] = (int)(~(unsigned int)(keys[p] & 0xFFFFFFFFu));
    } else if (bid < 68) {                        // ---- W converts ----
        const int gt = (bid - 4) * 1024 + tid;    // 65536 threads
        const float4* W4 = (const float4*)wadj;
        for (int i = gt; i < PP * PP / 4; i += 64 * 1024) {
            float4 v = W4[i];
            uint2 hp;
            hp.x = pack_h2(v.x, v.y); hp.y = pack_h2(v.z, v.w);
            *(uint2*)(g_W + (size_t)i * 4) = hp;
        }
        const float4* G4 = (const float4*)wwg;
        if (gt < CC * CC / 4) {
            float4 v = G4[gt];
            uint2 hp;
            hp.x = pack_h2(v.x, v.y); hp.y = pack_h2(v.z, v.w);
            *(uint2*)(g_WG + (size_t)gt * 4) = hp;
        }
    } else {                                      // ---- out = x ----
        const int gt = (bid - 68) * 1024 + tid;
        const float4* X4 = (const float4*)x;
        float4* O4 = (float4*)out;
        const int NT = BB * CC * HWN / 4;
        for (int i = gt; i < NT; i += 128 * 1024)
            O4[i] = X4[i];
    }
}

// ---------------- gather: x -> Gt fp16 [c][p] + Gf fp32 [p][c] ------
__global__ __launch_bounds__(256) void gather_kernel(const float* __restrict__ x)
{
    __shared__ float tile[64][65];
    __shared__ int jj[64];
    const int p0 = blockIdx.x * 64, c0 = blockIdx.y * 64, b = blockIdx.z;
    const int tid = threadIdx.x;
    if (tid < 64) jj[tid] = g_idx[b * PP + p0 + tid];
    __syncthreads();

    #pragma unroll
    for (int e = tid; e < 64 * 64; e += 256) {
        int pc = e & 63, cl = e >> 6;
        tile[pc][cl] = x[((size_t)b * CC + c0 + cl) * HWN + jj[pc]];
    }
    __syncthreads();

    #pragma unroll
    for (int e = tid; e < 64 * 64; e += 256) {
        int cl = e >> 6, pc = e & 63;
        g_Gt[((size_t)b * CC + c0 + cl) * PP + p0 + pc] =
            __float2half_rn(tile[pc][cl]);
    }
    #pragma unroll
    for (int e = tid; e < 64 * 64; e += 256) {
        int pc = e >> 6, cl = e & 63;
        g_Gf[((size_t)b * PP + p0 + pc) * CC + c0 + cl] = tile[pc][cl];
    }
}

// ---------------- mma.sync GEMM geometry ---------------------------
// CTA 128(M) x 64(N), BK=32, 256 thr, warps 4(m) x 2(n), warp 32x32.
// Plain fp16 single product. Stage: A[128][40], B[64][40]; 80B rows.
// STAGE = 15360 B, 2 stages.
#define STAGE 15360
#define ROWE  40

// Fragment load + MMA block shared by both GEMMs (warp 32x32)
#define FRAG_MMA(stb) \
    _Pragma("unroll") \
    for (int kk = 0; kk < 2; kk++) { \
        const int kb0 = kk * 16; \
        uint32_t ah[2][4], bh[2][4]; \
        _Pragma("unroll") \
        for (int mt = 0; mt < 2; mt++) { \
            uint32_t aaddr = (stb) + ((wm * 32 + mt * 16 + (lane & 15)) * ROWE \
                                      + kb0 + ((lane >> 4) << 3)) * 2; \
            LDSM4(ah[mt][0], ah[mt][1], ah[mt][2], ah[mt][3], aaddr); \
        } \
        _Pragma("unroll") \
        for (int u = 0; u < 2; u++) { \
            uint32_t baddr = (stb) + 10240 \
                + ((wn * 32 + u * 16 + ((lane >> 4) << 3) + (lane & 7)) * ROWE \
                   + kb0 + (((lane >> 3) & 1) << 3)) * 2; \
            LDSM4(bh[u][0], bh[u][1], bh[u][2], bh[u][3], baddr); \
        } \
        _Pragma("unroll") \
        for (int mt = 0; mt < 2; mt++) \
            _Pragma("unroll") \
            for (int nt = 0; nt < 4; nt++) { \
                const int u = nt >> 1, v = (nt & 1) * 2; \
                MMA_FP16(acc[mt][nt], ah[mt][0], ah[mt][1], ah[mt][2], ah[mt][3], \
                         bh[u][v], bh[u][v + 1]); \
            } \
    }

// ---------------- GEMM1: Z = relu(BN(W @ G)) + G --------------------
__global__ __launch_bounds__(256, 2) void gemm1_mma(
    const float* __restrict__ ga, const float* __restrict__ be)
{
    extern __shared__ __align__(16) char sm[];
    const uint32_t sb = smem_u32(sm);
    const int tid = threadIdx.x;
    const int b = blockIdx.z, m0 = blockIdx.y * 128, n0 = blockIdx.x * 64;
    const int lane = tid & 31, warp = tid >> 5;
    const int grp = lane >> 2, qid = lane & 3;
    const int wm = warp >> 1, wn = warp & 1;   // 4 m-warps x 2 n-warps

    float acc[2][4][4];
    #pragma unroll
    for (int i = 0; i < 2; i++)
        #pragma unroll
        for (int j = 0; j < 4; j++)
            #pragma unroll
            for (int r = 0; r < 4; r++) acc[i][j][r] = 0.0f;

#define G1_FILL(st, k0) do { \
    uint32_t base_ = sb + (st) * STAGE; \
    for (int i_ = tid; i_ < 512; i_ += 256) { \
        int r_ = i_ >> 2, c8_ = (i_ & 3) * 8; \
        uint32_t d_ = base_ + r_ * 80 + c8_ * 2; \
        CPA16(d_, g_W + (size_t)(m0 + r_) * PP + (k0) + c8_); \
    } \
    { \
        int i_ = tid; \
        int r_ = i_ >> 2, c8_ = (i_ & 3) * 8; \
        uint32_t d_ = base_ + 10240 + r_ * 80 + c8_ * 2; \
        CPA16(d_, g_Gt + ((size_t)b * CC + n0 + r_) * PP + (k0) + c8_); \
    } } while (0)

    G1_FILL(0, 0);
    CPA_COMMIT();

    const int NIT = PP / 32;   // 64
    #pragma unroll 1
    for (int it = 0; it < NIT; it++) {
        if (it + 1 < NIT) G1_FILL((it + 1) & 1, (it + 1) * 32);
        CPA_COMMIT();
        CPA_WAIT1();
        __syncthreads();
        const uint32_t stb = sb + (it & 1) * STAGE;
        FRAG_MMA(stb)
        __syncthreads();
    }

    const float inv = rsqrtf(1.0f + 1e-5f);
    #pragma unroll
    for (int mt = 0; mt < 2; mt++) {
        int row0 = m0 + wm * 32 + mt * 16 + grp;
        int row1 = row0 + 8;
        float s0 = inv * ga[row0], t0 = be[row0];
        float s1 = inv * ga[row1], t1 = be[row1];
        #pragma unroll
        for (int nt = 0; nt < 4; nt++) {
            int col = n0 + wn * 32 + nt * 8 + qid * 2;
            size_t o0 = ((size_t)b * PP + row0) * CC + col;
            size_t o1 = ((size_t)b * PP + row1) * CC + col;
            float2 gf0 = *(const float2*)(g_Gf + o0);
            float2 gf1 = *(const float2*)(g_Gf + o1);
            float v00 = fmaxf(fmaf(acc[mt][nt][0], s0, t0), 0.0f) + gf0.x;
            float v01 = fmaxf(fmaf(acc[mt][nt][1], s0, t0), 0.0f) + gf0.y;
            float v10 = fmaxf(fmaf(acc[mt][nt][2], s1, t1), 0.0f) + gf1.x;
            float v11 = fmaxf(fmaf(acc[mt][nt][3], s1, t1), 0.0f) + gf1.y;
            *(uint32_t*)(g_Z + o0) = pack_h2(v00, v01);
            *(uint32_t*)(g_Z + o1) = pack_h2(v10, v11);
        }
    }
#undef G1_FILL
}

// ---------------- GEMM2: R[b][d][p] = relu(BN(WG @ Z^T)), DENSE -----
__global__ __launch_bounds__(256, 2) void gemm2_mma(
    const float* __restrict__ gw, const float* __restrict__ bw)
{
    extern __shared__ __align__(16) char sm[];
    const uint32_t sb = smem_u32(sm);
    const int tid = threadIdx.x;
    const int b = blockIdx.z, m0 = blockIdx.y * 128, n0 = blockIdx.x * 64;
    const int lane = tid & 31, warp = tid >> 5;
    const int grp = lane >> 2, qid = lane & 3;
    const int wm = warp >> 1, wn = warp & 1;

    float acc[2][4][4];
    #pragma unroll
    for (int i = 0; i < 2; i++)
        #pragma unroll
        for (int j = 0; j < 4; j++)
            #pragma unroll
            for (int r = 0; r < 4; r++) acc[i][j][r] = 0.0f;

#define G2_FILL(st, k0) do { \
    uint32_t base_ = sb + (st) * STAGE; \
    for (int i_ = tid; i_ < 512; i_ += 256) { \
        int r_ = i_ >> 2, c8_ = (i_ & 3) * 8; \
        uint32_t d_ = base_ + r_ * 80 + c8_ * 2; \
        CPA16(d_, g_WG + (size_t)(m0 + r_) * CC + (k0) + c8_); \
    } \
    { \
        int i_ = tid; \
        int r_ = i_ >> 2, c8_ = (i_ & 3) * 8; \
        uint32_t d_ = base_ + 10240 + r_ * 80 + c8_ * 2; \
        CPA16(d_, g_Z + ((size_t)b * PP + n0 + r_) * CC + (k0) + c8_); \
    } } while (0)

    G2_FILL(0, 0);
    CPA_COMMIT();

    const int NIT = CC / 32;   // 8
    #pragma unroll 1
    for (int it = 0; it < NIT; it++) {
        if (it + 1 < NIT) G2_FILL((it + 1) & 1, (it + 1) * 32);
        CPA_COMMIT();
        CPA_WAIT1();
        __syncthreads();
        const uint32_t stb = sb + (it & 1) * STAGE;
        FRAG_MMA(stb)
        __syncthreads();
    }

    // dense epilogue: BN(axis=d) + ReLU -> R[b][d][p], coalesced float2
    const float inv = rsqrtf(1.0f + 1e-5f);
    #pragma unroll
    for (int mt = 0; mt < 2; mt++) {
        int row0 = m0 + wm * 32 + mt * 16 + grp;   // d
        int row1 = row0 + 8;
        float s0 = inv * gw[row0], t0 = bw[row0];
        float s1 = inv * gw[row1], t1 = bw[row1];
        #pragma unroll
        for (int nt = 0; nt < 4; nt++) {
            int col = n0 + wn * 32 + nt * 8 + qid * 2;   // p
            float2 v0, v1;
            v0.x = fmaxf(fmaf(acc[mt][nt][0], s0, t0), 0.0f);
            v0.y = fmaxf(fmaf(acc[mt][nt][1], s0, t0), 0.0f);
            v1.x = fmaxf(fmaf(acc[mt][nt][2], s1, t1), 0.0f);
            v1.y = fmaxf(fmaf(acc[mt][nt][3], s1, t1), 0.0f);
            *(float2*)(g_R + ((size_t)b * CC + row0) * PP + col) = v0;
            *(float2*)(g_R + ((size_t)b * CC + row1) * PP + col) = v1;
        }
    }
#undef G2_FILL
}

// ---------------- scatter: out[b][d][idx[p]] = R[b][d][p] -----------
__global__ __launch_bounds__(256) void scatter_kernel(float* __restrict__ out)
{
    __shared__ int jj[256];
    const int p0 = blockIdx.x * 256, d0 = blockIdx.y * 8, b = blockIdx.z;
    const int tid = threadIdx.x;
    jj[tid] = g_idx[b * PP + p0 + tid];
    __syncthreads();

    const int j = jj[tid];
    const float* Rb = g_R + ((size_t)b * CC + d0) * PP + p0 + tid;
    float* ob = out + ((size_t)b * CC + d0) * HWN + j;
    #pragma unroll
    for (int k = 0; k < 8; k++)
        ob[(size_t)k * HWN] = Rb[(size_t)k * PP];
}

// ---------------------------------------------------------------
extern "C" void kernel_launch(void* const* d_in, const int* in_sizes, int n_in,
                              void* d_out, int out_size)
{
    const float* x    = (const float*)d_in[0];
    const float* edge = (const float*)d_in[1];
    const float* wadj = (const float*)d_in[2];
    const float* ga   = (const float*)d_in[3];
    const float* be   = (const float*)d_in[4];
    const float* wwg  = (const float*)d_in[5];
    const float* gw   = (const float*)d_in[6];
    const float* bw   = (const float*)d_in[7];
    float* out = (float*)d_out;

    cudaFuncSetAttribute(prep_kernel, cudaFuncAttributeMaxDynamicSharedMemorySize, 65536);
    cudaFuncSetAttribute(gemm1_mma,   cudaFuncAttributeMaxDynamicSharedMemorySize, 2 * STAGE);
    cudaFuncSetAttribute(gemm2_mma,   cudaFuncAttributeMaxDynamicSharedMemorySize, 2 * STAGE);

    // fused: topk (0-3) + W converts (4-67) + out=x copy (68-195)
    prep_kernel<<<196, 1024, 65536>>>(edge, x, wadj, wwg, out);

    // gather (needs idx)
    {
        dim3 g(PP / 64, CC / 64, BB);   // (32, 4, 4)
        gather_kernel<<<g, 256>>>(x);
    }

    // GEMM1 + BN + ReLU + residual
    {
        dim3 g(CC / 64, PP / 128, BB);  // (4, 16, 4)
        gemm1_mma<<<g, 256, 2 * STAGE>>>(ga, be);
    }
    // GEMM2 + BN + ReLU -> dense R
    {
        dim3 g(PP / 64, CC / 128, BB);  // (32, 2, 4)
        gemm2_mma<<<g, 256, 2 * STAGE>>>(gw, bw);
    }
    // scatter R into out (out already = x from prep)
    {
        dim3 g(PP / 256, CC / 8, BB);   // (8, 32, 4)
        scatter_kernel<<<g, 256>>>(out);
    }
}